// round 1
// baseline (speedup 1.0000x reference)
#include <cuda_runtime.h>
#include <math.h>

// Problem constants
#define BB 16
#define NN 1024
#define FF 256
#define ALPHA 0.2f
#define NEG_BIG (-9.0e15f)

// Scratch (device globals — no allocations allowed)
__device__ float g_Wh[(size_t)BB * NN * FF];        // 16 MB
__device__ float g_f1[BB * NN];
__device__ float g_f2[BB * NN];
__device__ float g_P[(size_t)BB * NN * NN];         // 64 MB

// ---------------------------------------------------------------------------
// Generic 128x128x16 SGEMM, 256 threads, 8x8 per-thread microtile.
// C[M,Ncols] = A[M,K] * B[K,Ncols], all row-major. Optional ELU epilogue.
// Dims must be multiples of the tile (true for all uses here).
// ---------------------------------------------------------------------------
template <bool DO_ELU>
__global__ __launch_bounds__(256)
void sgemm128(const float* __restrict__ A, const float* __restrict__ B,
              float* __restrict__ C, int M, int Ncols, int K,
              size_t sA, size_t sB, size_t sC)
{
    constexpr int BM = 128, BN = 128, BK = 16;
    A += (size_t)blockIdx.z * sA;
    B += (size_t)blockIdx.z * sB;
    C += (size_t)blockIdx.z * sC;

    __shared__ float As[BK][BM];
    __shared__ float Bs[BK][BN];

    const int tid = threadIdx.x;
    const int tx  = tid & 15;    // 0..15 -> N direction
    const int ty  = tid >> 4;    // 0..15 -> M direction
    const int row0 = blockIdx.y * BM;
    const int col0 = blockIdx.x * BN;

    float acc[8][8];
#pragma unroll
    for (int i = 0; i < 8; i++)
#pragma unroll
        for (int j = 0; j < 8; j++) acc[i][j] = 0.f;

    for (int k0 = 0; k0 < K; k0 += BK) {
        // Load A tile (128x16) transposed into As, B tile (16x128) into Bs.
        // 512 float4 each; 2 per thread.
#pragma unroll
        for (int l = 0; l < 2; l++) {
            int idx = tid + l * 256;
            int arow = idx >> 2, ac = idx & 3;
            float4 va = *(const float4*)&A[(size_t)(row0 + arow) * K + k0 + ac * 4];
            As[ac * 4 + 0][arow] = va.x;
            As[ac * 4 + 1][arow] = va.y;
            As[ac * 4 + 2][arow] = va.z;
            As[ac * 4 + 3][arow] = va.w;
            int brow = idx >> 5, bc = idx & 31;
            *(float4*)&Bs[brow][bc * 4] =
                *(const float4*)&B[(size_t)(k0 + brow) * Ncols + col0 + bc * 4];
        }
        __syncthreads();

#pragma unroll
        for (int kk = 0; kk < BK; kk++) {
            float4 a0 = *(const float4*)&As[kk][ty * 8];
            float4 a1 = *(const float4*)&As[kk][ty * 8 + 4];
            float4 b0 = *(const float4*)&Bs[kk][tx * 8];
            float4 b1 = *(const float4*)&Bs[kk][tx * 8 + 4];
            float ar[8] = {a0.x, a0.y, a0.z, a0.w, a1.x, a1.y, a1.z, a1.w};
            float br[8] = {b0.x, b0.y, b0.z, b0.w, b1.x, b1.y, b1.z, b1.w};
#pragma unroll
            for (int i = 0; i < 8; i++)
#pragma unroll
                for (int j = 0; j < 8; j++)
                    acc[i][j] = fmaf(ar[i], br[j], acc[i][j]);
        }
        __syncthreads();
    }

#pragma unroll
    for (int i = 0; i < 8; i++) {
        int r = row0 + ty * 8 + i;
        float4 v0, v1;
        v0.x = acc[i][0]; v0.y = acc[i][1]; v0.z = acc[i][2]; v0.w = acc[i][3];
        v1.x = acc[i][4]; v1.y = acc[i][5]; v1.z = acc[i][6]; v1.w = acc[i][7];
        if (DO_ELU) {
            v0.x = v0.x > 0.f ? v0.x : expm1f(v0.x);
            v0.y = v0.y > 0.f ? v0.y : expm1f(v0.y);
            v0.z = v0.z > 0.f ? v0.z : expm1f(v0.z);
            v0.w = v0.w > 0.f ? v0.w : expm1f(v0.w);
            v1.x = v1.x > 0.f ? v1.x : expm1f(v1.x);
            v1.y = v1.y > 0.f ? v1.y : expm1f(v1.y);
            v1.z = v1.z > 0.f ? v1.z : expm1f(v1.z);
            v1.w = v1.w > 0.f ? v1.w : expm1f(v1.w);
        }
        float4* cp = (float4*)&C[(size_t)r * Ncols + col0 + tx * 8];
        cp[0] = v0;
        cp[1] = v1;
    }
}

// ---------------------------------------------------------------------------
// f1/f2: per-row dot of Wh row (256) with a1 = a[0:256], a2 = a[256:512]
// ---------------------------------------------------------------------------
__global__ __launch_bounds__(256)
void fkern(const float* __restrict__ Wh, const float* __restrict__ a,
           float* __restrict__ f1, float* __restrict__ f2)
{
    int row = blockIdx.x;
    int t = threadIdx.x;
    float w = Wh[(size_t)row * FF + t];
    float s1 = w * a[t];
    float s2 = w * a[FF + t];
#pragma unroll
    for (int o = 16; o > 0; o >>= 1) {
        s1 += __shfl_down_sync(0xffffffffu, s1, o);
        s2 += __shfl_down_sync(0xffffffffu, s2, o);
    }
    __shared__ float sh1[8], sh2[8];
    int warp = t >> 5, lane = t & 31;
    if (lane == 0) { sh1[warp] = s1; sh2[warp] = s2; }
    __syncthreads();
    if (t == 0) {
        float t1 = 0.f, t2 = 0.f;
#pragma unroll
        for (int w2 = 0; w2 < 8; w2++) { t1 += sh1[w2]; t2 += sh2[w2]; }
        f1[row] = t1;
        f2[row] = t2;
    }
}

// ---------------------------------------------------------------------------
// Masked leaky-relu + softmax over j. One block per (b,i) row.
// ---------------------------------------------------------------------------
__global__ __launch_bounds__(256)
void attn_softmax(const int* __restrict__ adj, float* __restrict__ P,
                  const float* __restrict__ f1, const float* __restrict__ f2)
{
    int row = blockIdx.x;           // b*N + i
    int t = threadIdx.x;
    int b = row >> 10;
    float f1v = f1[row];

    __shared__ float ebuf[NN];
    __shared__ float red_m[8];
    __shared__ float red_s[8];

    int warp = t >> 5, lane = t & 31;

    float lmax = -INFINITY;
#pragma unroll
    for (int c = 0; c < 4; c++) {
        int j = (c << 8) + t;
        float s = f1v + f2[(b << 10) + j];
        float e = s >= 0.f ? s : ALPHA * s;
        int av = adj[(size_t)row * NN + j];
        float v = (av > 0) ? e : NEG_BIG;
        ebuf[j] = v;
        lmax = fmaxf(lmax, v);
    }
#pragma unroll
    for (int o = 16; o > 0; o >>= 1)
        lmax = fmaxf(lmax, __shfl_xor_sync(0xffffffffu, lmax, o));
    if (lane == 0) red_m[warp] = lmax;
    __syncthreads();
    float m = red_m[0];
#pragma unroll
    for (int w2 = 1; w2 < 8; w2++) m = fmaxf(m, red_m[w2]);

    float p[4];
    float lsum = 0.f;
#pragma unroll
    for (int c = 0; c < 4; c++) {
        int j = (c << 8) + t;
        p[c] = __expf(ebuf[j] - m);
        lsum += p[c];
    }
#pragma unroll
    for (int o = 16; o > 0; o >>= 1)
        lsum += __shfl_xor_sync(0xffffffffu, lsum, o);
    if (lane == 0) red_s[warp] = lsum;
    __syncthreads();
    float denom = 0.f;
#pragma unroll
    for (int w2 = 0; w2 < 8; w2++) denom += red_s[w2];
    float inv = 1.0f / denom;

#pragma unroll
    for (int c = 0; c < 4; c++) {
        int j = (c << 8) + t;
        P[(size_t)row * NN + j] = p[c] * inv;
    }
}

// ---------------------------------------------------------------------------
// Launch
// ---------------------------------------------------------------------------
extern "C" void kernel_launch(void* const* d_in, const int* in_sizes, int n_in,
                              void* d_out, int out_size)
{
    const float* h   = (const float*)d_in[0];   // [16,1024,256]
    const int*   adj = (const int*)d_in[1];     // [16,1024,1024]
    const float* W   = (const float*)d_in[2];   // [256,256]
    const float* a   = (const float*)d_in[3];   // [512,1]
    float* out = (float*)d_out;                 // [16,1024,256]

    float *Wh, *f1, *f2, *P;
    cudaGetSymbolAddress((void**)&Wh, g_Wh);
    cudaGetSymbolAddress((void**)&f1, g_f1);
    cudaGetSymbolAddress((void**)&f2, g_f2);
    cudaGetSymbolAddress((void**)&P,  g_P);

    // 1) Wh = h @ W   (flattened: [16384,256] = [16384,256] x [256,256])
    sgemm128<false><<<dim3(FF / 128, (BB * NN) / 128, 1), 256>>>(
        h, W, Wh, BB * NN, FF, FF, 0, 0, 0);

    // 2) f1, f2
    fkern<<<BB * NN, 256>>>(Wh, a, f1, f2);

    // 3) masked softmax -> P
    attn_softmax<<<BB * NN, 256>>>(adj, P, f1, f2);

    // 4) out = elu(P @ Wh), batched
    sgemm128<true><<<dim3(FF / 128, NN / 128, BB), 256>>>(
        P, Wh, out, NN, FF, NN,
        (size_t)NN * NN, (size_t)NN * FF, (size_t)NN * FF);
}

// round 5
// speedup vs baseline: 1.7732x; 1.7732x over previous
#include <cuda_runtime.h>
#include <math.h>
#include <stdint.h>

// Problem constants
#define BB 16
#define NN 1024
#define FF 256
#define ALPHA 0.2f
#define NEG_BIG (-9.0e15f)

// Scratch (device globals — no allocations allowed)
__device__ float g_Wh[(size_t)BB * NN * FF];        // 16 MB  [b][j][o]
__device__ float g_f1[BB * NN];
__device__ float g_f2[BB * NN];
__device__ float g_P[(size_t)BB * NN * NN];         // 64 MB

// ---------------------------------------------------------------------------
// fp32 SGEMM (R1-proven): 128x128x16 tile, 256 threads, 8x8 microtile.
// C[M,N] = A[M,K] * B[K,N], row-major.
// ---------------------------------------------------------------------------
__global__ __launch_bounds__(256)
void sgemm128(const float* __restrict__ A, const float* __restrict__ B,
              float* __restrict__ C, int M, int Ncols, int K)
{
    constexpr int BK = 16;
    __shared__ float As[BK][128];
    __shared__ float Bs[BK][128];

    const int tid = threadIdx.x;
    const int tx  = tid & 15;
    const int ty  = tid >> 4;
    const int row0 = blockIdx.y * 128;
    const int col0 = blockIdx.x * 128;

    float acc[8][8];
#pragma unroll
    for (int i = 0; i < 8; i++)
#pragma unroll
        for (int j = 0; j < 8; j++) acc[i][j] = 0.f;

    for (int k0 = 0; k0 < K; k0 += BK) {
#pragma unroll
        for (int l = 0; l < 2; l++) {
            int idx = tid + l * 256;
            int arow = idx >> 2, ac = idx & 3;
            float4 va = *(const float4*)&A[(size_t)(row0 + arow) * K + k0 + ac * 4];
            As[ac * 4 + 0][arow] = va.x;
            As[ac * 4 + 1][arow] = va.y;
            As[ac * 4 + 2][arow] = va.z;
            As[ac * 4 + 3][arow] = va.w;
            int brow = idx >> 5, bc = idx & 31;
            *(float4*)&Bs[brow][bc * 4] =
                *(const float4*)&B[(size_t)(k0 + brow) * Ncols + col0 + bc * 4];
        }
        __syncthreads();

#pragma unroll
        for (int kk = 0; kk < BK; kk++) {
            float4 a0 = *(const float4*)&As[kk][ty * 8];
            float4 a1 = *(const float4*)&As[kk][ty * 8 + 4];
            float4 b0 = *(const float4*)&Bs[kk][tx * 8];
            float4 b1 = *(const float4*)&Bs[kk][tx * 8 + 4];
            float ar[8] = {a0.x, a0.y, a0.z, a0.w, a1.x, a1.y, a1.z, a1.w};
            float br[8] = {b0.x, b0.y, b0.z, b0.w, b1.x, b1.y, b1.z, b1.w};
#pragma unroll
            for (int i = 0; i < 8; i++)
#pragma unroll
                for (int j = 0; j < 8; j++)
                    acc[i][j] = fmaf(ar[i], br[j], acc[i][j]);
        }
        __syncthreads();
    }

#pragma unroll
    for (int i = 0; i < 8; i++) {
        int r = row0 + ty * 8 + i;
        float4 v0, v1;
        v0.x = acc[i][0]; v0.y = acc[i][1]; v0.z = acc[i][2]; v0.w = acc[i][3];
        v1.x = acc[i][4]; v1.y = acc[i][5]; v1.z = acc[i][6]; v1.w = acc[i][7];
        float4* cp = (float4*)&C[(size_t)r * Ncols + col0 + tx * 8];
        cp[0] = v0;
        cp[1] = v1;
    }
}

// ---------------------------------------------------------------------------
// f1/f2: per-row dot of Wh row (256) with a1 = a[0:256], a2 = a[256:512]
// ---------------------------------------------------------------------------
__global__ __launch_bounds__(256)
void fkern(const float* __restrict__ Wh, const float* __restrict__ a,
           float* __restrict__ f1, float* __restrict__ f2)
{
    int row = blockIdx.x;
    int t = threadIdx.x;
    float w = Wh[(size_t)row * FF + t];
    float s1 = w * a[t];
    float s2 = w * a[FF + t];
#pragma unroll
    for (int o = 16; o > 0; o >>= 1) {
        s1 += __shfl_down_sync(0xffffffffu, s1, o);
        s2 += __shfl_down_sync(0xffffffffu, s2, o);
    }
    __shared__ float sh1[8], sh2[8];
    int warp = t >> 5, lane = t & 31;
    if (lane == 0) { sh1[warp] = s1; sh2[warp] = s2; }
    __syncthreads();
    if (t == 0) {
        float t1 = 0.f, t2 = 0.f;
#pragma unroll
        for (int w2 = 0; w2 < 8; w2++) { t1 += sh1[w2]; t2 += sh2[w2]; }
        f1[row] = t1;
        f2[row] = t2;
    }
}

// ---------------------------------------------------------------------------
// Masked leaky-relu + softmax over j. One block per (b,i) row. (R1-proven)
// ---------------------------------------------------------------------------
__global__ __launch_bounds__(256)
void attn_softmax(const int* __restrict__ adj, float* __restrict__ P,
                  const float* __restrict__ f1, const float* __restrict__ f2)
{
    int row = blockIdx.x;           // b*N + i
    int t = threadIdx.x;
    int b = row >> 10;
    float f1v = f1[row];

    __shared__ float ebuf[NN];
    __shared__ float red_m[8];
    __shared__ float red_s[8];

    int warp = t >> 5, lane = t & 31;

    float lmax = -INFINITY;
#pragma unroll
    for (int c = 0; c < 4; c++) {
        int j = (c << 8) + t;
        float s = f1v + f2[(b << 10) + j];
        float e = s >= 0.f ? s : ALPHA * s;
        int av = adj[(size_t)row * NN + j];
        float v = (av > 0) ? e : NEG_BIG;
        ebuf[j] = v;
        lmax = fmaxf(lmax, v);
    }
#pragma unroll
    for (int o = 16; o > 0; o >>= 1)
        lmax = fmaxf(lmax, __shfl_xor_sync(0xffffffffu, lmax, o));
    if (lane == 0) red_m[warp] = lmax;
    __syncthreads();
    float m = red_m[0];
#pragma unroll
    for (int w2 = 1; w2 < 8; w2++) m = fmaxf(m, red_m[w2]);

    float p[4];
    float lsum = 0.f;
#pragma unroll
    for (int c = 0; c < 4; c++) {
        int j = (c << 8) + t;
        p[c] = __expf(ebuf[j] - m);
        lsum += p[c];
    }
#pragma unroll
    for (int o = 16; o > 0; o >>= 1)
        lsum += __shfl_xor_sync(0xffffffffu, lsum, o);
    if (lane == 0) red_s[warp] = lsum;
    __syncthreads();
    float denom = 0.f;
#pragma unroll
    for (int w2 = 0; w2 < 8; w2++) denom += red_s[w2];
    float inv = 1.0f / denom;

#pragma unroll
    for (int c = 0; c < 4; c++) {
        int j = (c << 8) + t;
        P[(size_t)row * NN + j] = p[c] * inv;
    }
}

// ===========================================================================
// GEMM2 via mma.sync (tf32 HMMA, baseline PTX — no 'a'-gated features):
//   out[z] = elu( P[z] (1024x1024) @ Wh[z] (1024x256) )
// Block 128x128, BK=32, 8 warps, warp tile 32x64, m16n8k8 tf32 fragments.
// ===========================================================================
#define BK2 32
#define APAD 36     // As[m][k]: bank = (4m + k) % 32 -> conflict-free frag loads
#define BPAD 136    // Bs[k][n]: bank = (8k + n) % 32 -> conflict-free frag loads

__device__ __forceinline__ uint32_t f2tf32(float x) {
    uint32_t r;
    asm("cvt.rna.tf32.f32 %0, %1;" : "=r"(r) : "f"(x));
    return r;
}

__device__ __forceinline__ void mma_tf32(float* c, const uint32_t* a, const uint32_t* b) {
    asm volatile(
        "mma.sync.aligned.m16n8k8.row.col.f32.tf32.tf32.f32 "
        "{%0,%1,%2,%3}, {%4,%5,%6,%7}, {%8,%9}, {%0,%1,%2,%3};"
        : "+f"(c[0]), "+f"(c[1]), "+f"(c[2]), "+f"(c[3])
        : "r"(a[0]), "r"(a[1]), "r"(a[2]), "r"(a[3]), "r"(b[0]), "r"(b[1]));
}

__global__ __launch_bounds__(256)
void gemm2_mma(const float* __restrict__ P, const float* __restrict__ Wh,
               float* __restrict__ out)
{
    __shared__ uint32_t As[128][APAD];   // [m][k]
    __shared__ uint32_t Bs[BK2][BPAD];   // [k][n]

    const int tid = threadIdx.x;
    const int wid = tid >> 5;
    const int lane = tid & 31;
    const int wm = wid & 3;              // 4 warp rows of 32
    const int wn = wid >> 2;             // 2 warp cols of 64
    const int qid = lane >> 2;           // lane/4: 0..7
    const int qtr = lane & 3;            // lane%4: 0..3

    const float* Az = P + (size_t)blockIdx.z * NN * NN + (size_t)(blockIdx.y * 128) * NN;
    const float* Bz = Wh + (size_t)blockIdx.z * NN * FF + blockIdx.x * 128;
    float* Cz = out + (size_t)blockIdx.z * NN * FF;

    float acc[2][8][4];
#pragma unroll
    for (int i = 0; i < 2; i++)
#pragma unroll
        for (int j = 0; j < 8; j++)
#pragma unroll
            for (int c = 0; c < 4; c++) acc[i][j][c] = 0.f;

    for (int k0 = 0; k0 < NN; k0 += BK2) {
        // A tile: 128 rows x 32 cols; 1024 float4 -> 4 per thread
#pragma unroll
        for (int l = 0; l < 4; l++) {
            int idx = tid + l * 256;
            int r = idx >> 3, kc = idx & 7;
            float4 v = *(const float4*)(Az + (size_t)r * NN + k0 + kc * 4);
            uint32_t* dst = &As[r][kc * 4];
            dst[0] = f2tf32(v.x); dst[1] = f2tf32(v.y);
            dst[2] = f2tf32(v.z); dst[3] = f2tf32(v.w);
        }
        // B tile: 32 rows x 128 cols; 1024 float4 -> 4 per thread
#pragma unroll
        for (int l = 0; l < 4; l++) {
            int idx = tid + l * 256;
            int kr = idx >> 5, nc = idx & 31;
            float4 v = *(const float4*)(Bz + (size_t)(k0 + kr) * FF + nc * 4);
            uint32_t* dst = &Bs[kr][nc * 4];
            dst[0] = f2tf32(v.x); dst[1] = f2tf32(v.y);
            dst[2] = f2tf32(v.z); dst[3] = f2tf32(v.w);
        }
        __syncthreads();

#pragma unroll
        for (int kk = 0; kk < BK2 / 8; kk++) {
            const int kb = kk * 8;
            // A fragments: 2 m-frags x 4 regs
            uint32_t af[2][4];
#pragma unroll
            for (int mf = 0; mf < 2; mf++) {
                int mrow = wm * 32 + mf * 16 + qid;
                af[mf][0] = As[mrow][kb + qtr];
                af[mf][1] = As[mrow + 8][kb + qtr];
                af[mf][2] = As[mrow][kb + qtr + 4];
                af[mf][3] = As[mrow + 8][kb + qtr + 4];
            }
            // B fragments: 8 n-frags x 2 regs
            uint32_t bf[8][2];
#pragma unroll
            for (int nf = 0; nf < 8; nf++) {
                int ncol = wn * 64 + nf * 8 + qid;
                bf[nf][0] = Bs[kb + qtr][ncol];
                bf[nf][1] = Bs[kb + qtr + 4][ncol];
            }
#pragma unroll
            for (int mf = 0; mf < 2; mf++)
#pragma unroll
                for (int nf = 0; nf < 8; nf++)
                    mma_tf32(acc[mf][nf], af[mf], bf[nf]);
        }
        __syncthreads();
    }

    // Epilogue: ELU + store. c0,c1 -> row qid; c2,c3 -> row qid+8.
    const int row_base = blockIdx.y * 128 + wm * 32;
    const int col_base = blockIdx.x * 128 + wn * 64;
#pragma unroll
    for (int mf = 0; mf < 2; mf++) {
#pragma unroll
        for (int half = 0; half < 2; half++) {
            int r = row_base + mf * 16 + qid + half * 8;
            float* crow = Cz + (size_t)r * FF;
#pragma unroll
            for (int nf = 0; nf < 8; nf++) {
                float x0 = acc[mf][nf][half * 2];
                float x1 = acc[mf][nf][half * 2 + 1];
                float2 v;
                v.x = x0 > 0.f ? x0 : expm1f(x0);
                v.y = x1 > 0.f ? x1 : expm1f(x1);
                *(float2*)(crow + col_base + nf * 8 + qtr * 2) = v;
            }
        }
    }
}

// ---------------------------------------------------------------------------
// Launch
// ---------------------------------------------------------------------------
extern "C" void kernel_launch(void* const* d_in, const int* in_sizes, int n_in,
                              void* d_out, int out_size)
{
    const float* h   = (const float*)d_in[0];   // [16,1024,256]
    const int*   adj = (const int*)d_in[1];     // [16,1024,1024]
    const float* W   = (const float*)d_in[2];   // [256,256]
    const float* a   = (const float*)d_in[3];   // [512,1]
    float* out = (float*)d_out;                 // [16,1024,256]

    float *Wh, *f1, *f2, *P;
    cudaGetSymbolAddress((void**)&Wh, g_Wh);
    cudaGetSymbolAddress((void**)&f1, g_f1);
    cudaGetSymbolAddress((void**)&f2, g_f2);
    cudaGetSymbolAddress((void**)&P,  g_P);

    // 1) Wh = h @ W  (fp32 SGEMM, proven — keeps softmax logits fp32-exact)
    sgemm128<<<dim3(FF / 128, (BB * NN) / 128), 256>>>(h, W, Wh, BB * NN, FF, FF);

    // 2) f1, f2 (fp32, proven)
    fkern<<<BB * NN, 256>>>(Wh, a, f1, f2);

    // 3) masked softmax -> P (proven)
    attn_softmax<<<BB * NN, 256>>>(adj, P, f1, f2);

    // 4) out = elu(P @ Wh)  — tf32 mma.sync tensor path
    gemm2_mma<<<dim3(FF / 128, NN / 128, BB), 256>>>(P, Wh, out);
}

// round 7
// speedup vs baseline: 2.3518x; 1.3263x over previous
#include <cuda_runtime.h>
#include <math.h>
#include <stdint.h>

// Problem constants
#define BB 16
#define NN 1024
#define FF 256
#define ALPHA 0.2f
#define NEG_BIG (-9.0e15f)

// Scratch (device globals — no allocations allowed)
__device__ float g_Wh[(size_t)BB * NN * FF];        // 16 MB  [b][j][o]
__device__ float g_u[2 * FF];                       // u1 = W@a1, u2 = W@a2
__device__ float g_f1[BB * NN];
__device__ float g_f2[BB * NN];
__device__ float g_P[(size_t)BB * NN * NN];         // 64 MB

// ---------------------------------------------------------------------------
// Helpers
// ---------------------------------------------------------------------------
__device__ __forceinline__ uint32_t smem_u32(const void* p) {
    uint32_t a;
    asm("{ .reg .u64 t; cvta.to.shared.u64 t, %1; cvt.u32.u64 %0, t; }"
        : "=r"(a) : "l"(p));
    return a;
}

__device__ __forceinline__ void cp16(uint32_t saddr, const void* gptr) {
    asm volatile("cp.async.cg.shared.global [%0], [%1], 16;"
                 :: "r"(saddr), "l"(gptr) : "memory");
}

__device__ __forceinline__ void mma_tf32(float* c, const uint32_t* a, const uint32_t* b) {
    asm volatile(
        "mma.sync.aligned.m16n8k8.row.col.f32.tf32.tf32.f32 "
        "{%0,%1,%2,%3}, {%4,%5,%6,%7}, {%8,%9}, {%0,%1,%2,%3};"
        : "+f"(c[0]), "+f"(c[1]), "+f"(c[2]), "+f"(c[3])
        : "r"(a[0]), "r"(a[1]), "r"(a[2]), "r"(a[3]), "r"(b[0]), "r"(b[1]));
}

// ===========================================================================
// Unified tf32 mma GEMM: C[z] = (elu?)( A[z] (MxK) @ B[z] (KxN) ), row-major.
// Block 128x128, BK=32, 8 warps (warp tile 32x64), cp.async double-buffered.
// Fragments rounded to tf32-rna via +0x1000 (HW truncates low 13 bits).
// ===========================================================================
#define BM 128
#define BN 128
#define BK 32
#define APADF 36     // As[m][k] pad: bank = (4m + k) % 32, conflict-free
#define BPADF 136    // Bs[k][n] pad: bank = (8k + n) % 32, conflict-free
#define A_TILE_F (BM * APADF)            // 4608 floats
#define B_TILE_F (BK * BPADF)            // 4352 floats
#define STAGE_F (A_TILE_F + B_TILE_F)    // 8960 floats
#define GEMM_SMEM (2 * STAGE_F * 4)      // 71680 bytes

template <bool DO_ELU>
__global__ __launch_bounds__(256)
void gemm_tf32(const float* __restrict__ A, const float* __restrict__ B,
               float* __restrict__ C, int K, int ldA, int ldB, int ldC,
               size_t sA, size_t sB, size_t sC)
{
    extern __shared__ float smf[];
    const uint32_t sbase = smem_u32(smf);

    const int tid = threadIdx.x;
    const int wid = tid >> 5;
    const int lane = tid & 31;
    const int wm = wid & 3;              // 4 warp rows of 32
    const int wn = wid >> 2;             // 2 warp cols of 64
    const int qid = lane >> 2;           // 0..7
    const int qtr = lane & 3;            // 0..3

    const float* Az = A + (size_t)blockIdx.z * sA + (size_t)(blockIdx.y * BM) * ldA;
    const float* Bz = B + (size_t)blockIdx.z * sB + blockIdx.x * BN;
    float* Cz = C + (size_t)blockIdx.z * sC;

    float acc[2][8][4];
#pragma unroll
    for (int i = 0; i < 2; i++)
#pragma unroll
        for (int j = 0; j < 8; j++)
#pragma unroll
            for (int c = 0; c < 4; c++) acc[i][j][c] = 0.f;

    auto issue_tile = [&](int t, int stage) {
        const float* Aa = Az + t * BK;
        const float* Ba = Bz + (size_t)(t * BK) * ldB;
        const uint32_t abase = sbase + stage * (STAGE_F * 4);
        const uint32_t bbase = abase + A_TILE_F * 4;
#pragma unroll
        for (int l = 0; l < 4; l++) {
            int idx = tid + l * 256;
            int r = idx >> 3, kc = idx & 7;
            cp16(abase + (uint32_t)(r * APADF + kc * 4) * 4,
                 Aa + (size_t)r * ldA + kc * 4);
        }
#pragma unroll
        for (int l = 0; l < 4; l++) {
            int idx = tid + l * 256;
            int kr = idx >> 5, nc = idx & 31;
            cp16(bbase + (uint32_t)(kr * BPADF + nc * 4) * 4,
                 Ba + (size_t)kr * ldB + nc * 4);
        }
        asm volatile("cp.async.commit_group;" ::: "memory");
    };

    const int T = K / BK;
    issue_tile(0, 0);

    for (int t = 0; t < T; t++) {
        const int cur = t & 1;
        if (t + 1 < T) {
            issue_tile(t + 1, cur ^ 1);
            asm volatile("cp.async.wait_group 1;" ::: "memory");
        } else {
            asm volatile("cp.async.wait_group 0;" ::: "memory");
        }
        __syncthreads();

        const uint32_t* As = (const uint32_t*)smf + cur * STAGE_F;
        const uint32_t* Bs = As + A_TILE_F;

#pragma unroll
        for (int kk = 0; kk < BK / 8; kk++) {
            const int kb = kk * 8;
            uint32_t af[2][4];
#pragma unroll
            for (int mf = 0; mf < 2; mf++) {
                int mrow = wm * 32 + mf * 16 + qid;
                af[mf][0] = As[mrow * APADF + kb + qtr] + 0x1000u;
                af[mf][1] = As[(mrow + 8) * APADF + kb + qtr] + 0x1000u;
                af[mf][2] = As[mrow * APADF + kb + qtr + 4] + 0x1000u;
                af[mf][3] = As[(mrow + 8) * APADF + kb + qtr + 4] + 0x1000u;
            }
            uint32_t bf[8][2];
#pragma unroll
            for (int nf = 0; nf < 8; nf++) {
                int ncol = wn * 64 + nf * 8 + qid;
                bf[nf][0] = Bs[(kb + qtr) * BPADF + ncol] + 0x1000u;
                bf[nf][1] = Bs[(kb + qtr + 4) * BPADF + ncol] + 0x1000u;
            }
#pragma unroll
            for (int mf = 0; mf < 2; mf++)
#pragma unroll
                for (int nf = 0; nf < 8; nf++)
                    mma_tf32(acc[mf][nf], af[mf], bf[nf]);
        }
        __syncthreads();
    }

    // Epilogue. c0,c1 -> row qid; c2,c3 -> row qid+8.
    const int row_base = blockIdx.y * BM + wm * 32;
    const int col_base = blockIdx.x * BN + wn * 64;
#pragma unroll
    for (int mf = 0; mf < 2; mf++) {
#pragma unroll
        for (int half = 0; half < 2; half++) {
            int r = row_base + mf * 16 + qid + half * 8;
            float* crow = Cz + (size_t)r * ldC;
#pragma unroll
            for (int nf = 0; nf < 8; nf++) {
                float x0 = acc[mf][nf][half * 2];
                float x1 = acc[mf][nf][half * 2 + 1];
                float2 v;
                if (DO_ELU) {
                    v.x = x0 > 0.f ? x0 : expm1f(x0);
                    v.y = x1 > 0.f ? x1 : expm1f(x1);
                } else {
                    v.x = x0; v.y = x1;
                }
                *(float2*)(crow + col_base + nf * 8 + qtr * 2) = v;
            }
        }
    }
}

// ---------------------------------------------------------------------------
// u1 = W @ a1, u2 = W @ a2  (one block per f, 256 threads over o; fp32)
// ---------------------------------------------------------------------------
__global__ __launch_bounds__(256)
void ukern(const float* __restrict__ W, const float* __restrict__ a,
           float* __restrict__ u)
{
    int f = blockIdx.x;
    int o = threadIdx.x;
    float w = W[f * FF + o];
    float s1 = w * a[o];
    float s2 = w * a[FF + o];
#pragma unroll
    for (int off = 16; off > 0; off >>= 1) {
        s1 += __shfl_down_sync(0xffffffffu, s1, off);
        s2 += __shfl_down_sync(0xffffffffu, s2, off);
    }
    __shared__ float sh1[8], sh2[8];
    int warp = o >> 5, lane = o & 31;
    if (lane == 0) { sh1[warp] = s1; sh2[warp] = s2; }
    __syncthreads();
    if (o == 0) {
        float t1 = 0.f, t2 = 0.f;
#pragma unroll
        for (int w2 = 0; w2 < 8; w2++) { t1 += sh1[w2]; t2 += sh2[w2]; }
        u[f] = t1;
        u[FF + f] = t2;
    }
}

// ---------------------------------------------------------------------------
// f1[r] = h_row . u1, f2[r] = h_row . u2   (fp32 — logits stay exact)
// ---------------------------------------------------------------------------
__global__ __launch_bounds__(256)
void fkern2(const float* __restrict__ h, const float* __restrict__ u,
            float* __restrict__ f1, float* __restrict__ f2)
{
    int row = blockIdx.x;
    int t = threadIdx.x;
    float hv = h[(size_t)row * FF + t];
    float s1 = hv * u[t];
    float s2 = hv * u[FF + t];
#pragma unroll
    for (int o = 16; o > 0; o >>= 1) {
        s1 += __shfl_down_sync(0xffffffffu, s1, o);
        s2 += __shfl_down_sync(0xffffffffu, s2, o);
    }
    __shared__ float sh1[8], sh2[8];
    int warp = t >> 5, lane = t & 31;
    if (lane == 0) { sh1[warp] = s1; sh2[warp] = s2; }
    __syncthreads();
    if (t == 0) {
        float t1 = 0.f, t2 = 0.f;
#pragma unroll
        for (int w2 = 0; w2 < 8; w2++) { t1 += sh1[w2]; t2 += sh2[w2]; }
        f1[row] = t1;
        f2[row] = t2;
    }
}

// ---------------------------------------------------------------------------
// Masked leaky-relu + softmax over j. One block per (b,i) row. (proven)
// ---------------------------------------------------------------------------
__global__ __launch_bounds__(256)
void attn_softmax(const int* __restrict__ adj, float* __restrict__ P,
                  const float* __restrict__ f1, const float* __restrict__ f2)
{
    int row = blockIdx.x;           // b*N + i
    int t = threadIdx.x;
    int b = row >> 10;
    float f1v = f1[row];

    __shared__ float ebuf[NN];
    __shared__ float red_m[8];
    __shared__ float red_s[8];

    int warp = t >> 5, lane = t & 31;

    float lmax = -INFINITY;
#pragma unroll
    for (int c = 0; c < 4; c++) {
        int j = (c << 8) + t;
        float s = f1v + f2[(b << 10) + j];
        float e = s >= 0.f ? s : ALPHA * s;
        int av = adj[(size_t)row * NN + j];
        float v = (av > 0) ? e : NEG_BIG;
        ebuf[j] = v;
        lmax = fmaxf(lmax, v);
    }
#pragma unroll
    for (int o = 16; o > 0; o >>= 1)
        lmax = fmaxf(lmax, __shfl_xor_sync(0xffffffffu, lmax, o));
    if (lane == 0) red_m[warp] = lmax;
    __syncthreads();
    float m = red_m[0];
#pragma unroll
    for (int w2 = 1; w2 < 8; w2++) m = fmaxf(m, red_m[w2]);

    float p[4];
    float lsum = 0.f;
#pragma unroll
    for (int c = 0; c < 4; c++) {
        int j = (c << 8) + t;
        p[c] = __expf(ebuf[j] - m);
        lsum += p[c];
    }
#pragma unroll
    for (int o = 16; o > 0; o >>= 1)
        lsum += __shfl_xor_sync(0xffffffffu, lsum, o);
    if (lane == 0) red_s[warp] = lsum;
    __syncthreads();
    float denom = 0.f;
#pragma unroll
    for (int w2 = 0; w2 < 8; w2++) denom += red_s[w2];
    float inv = 1.0f / denom;

#pragma unroll
    for (int c = 0; c < 4; c++) {
        int j = (c << 8) + t;
        P[(size_t)row * NN + j] = p[c] * inv;
    }
}

// ---------------------------------------------------------------------------
// Launch
// ---------------------------------------------------------------------------
extern "C" void kernel_launch(void* const* d_in, const int* in_sizes, int n_in,
                              void* d_out, int out_size)
{
    const float* h   = (const float*)d_in[0];   // [16,1024,256]
    const int*   adj = (const int*)d_in[1];     // [16,1024,1024]
    const float* W   = (const float*)d_in[2];   // [256,256]
    const float* a   = (const float*)d_in[3];   // [512,1]
    float* out = (float*)d_out;                 // [16,1024,256]

    float *Wh, *u, *f1, *f2, *P;
    cudaGetSymbolAddress((void**)&Wh, g_Wh);
    cudaGetSymbolAddress((void**)&u,  g_u);
    cudaGetSymbolAddress((void**)&f1, g_f1);
    cudaGetSymbolAddress((void**)&f2, g_f2);
    cudaGetSymbolAddress((void**)&P,  g_P);

    cudaFuncSetAttribute(gemm_tf32<false>, cudaFuncAttributeMaxDynamicSharedMemorySize, GEMM_SMEM);
    cudaFuncSetAttribute(gemm_tf32<true>,  cudaFuncAttributeMaxDynamicSharedMemorySize, GEMM_SMEM);

    // 1) u1,u2 = W@a1, W@a2 (fp32)
    ukern<<<FF, 256>>>(W, a, u);

    // 2) f1,f2 = h@u1, h@u2 (fp32 — softmax logits exact)
    fkern2<<<BB * NN, 256>>>(h, u, f1, f2);

    // 3) Wh = h @ W  (tf32 mma, pipelined)
    gemm_tf32<false><<<dim3(FF / BN, (BB * NN) / BM, 1), 256, GEMM_SMEM>>>(
        h, W, Wh, FF, FF, FF, FF, 0, 0, 0);

    // 4) masked softmax -> P (proven)
    attn_softmax<<<BB * NN, 256>>>(adj, P, f1, f2);

    // 5) out = elu(P @ Wh)  (tf32 mma, pipelined)
    gemm_tf32<true><<<dim3(FF / BN, NN / BM, BB), 256, GEMM_SMEM>>>(
        P, Wh, out, NN, NN, FF, FF,
        (size_t)NN * NN, (size_t)NN * FF, (size_t)NN * FF);
}

// round 8
// speedup vs baseline: 2.4914x; 1.0594x over previous
#include <cuda_runtime.h>
#include <math.h>
#include <stdint.h>

// Problem constants
#define BB 16
#define NN 1024
#define FF 256
#define ALPHA 0.2f

// Scratch (device globals — no allocations allowed)
__device__ float g_Wh[(size_t)BB * NN * FF];        // 16 MB  [b][j][o], tf32-rounded
__device__ float g_u[2 * FF];                       // u1 = W@a1, u2 = W@a2
__device__ float g_f1[BB * NN];
__device__ float g_f2[BB * NN];
__device__ float g_P[(size_t)BB * NN * NN];         // 64 MB, unnormalized exp, tf32-rounded
__device__ float g_invden[BB * NN];                 // 1 / row sum

// ---------------------------------------------------------------------------
// Helpers
// ---------------------------------------------------------------------------
__device__ __forceinline__ void cp16(uint32_t saddr, const void* gptr) {
    asm volatile("cp.async.cg.shared.global [%0], [%1], 16;"
                 :: "r"(saddr), "l"(gptr) : "memory");
}

__device__ __forceinline__ uint32_t smem_u32(const void* p) {
    uint32_t a;
    asm("{ .reg .u64 t; cvta.to.shared.u64 t, %1; cvt.u32.u64 %0, t; }"
        : "=r"(a) : "l"(p));
    return a;
}

__device__ __forceinline__ float rna_tf32(float x) {
    uint32_t r;
    asm("cvt.rna.tf32.f32 %0, %1;" : "=r"(r) : "f"(x));
    return __uint_as_float(r);
}

__device__ __forceinline__ void mma_tf32(float* c, const uint32_t* a, const uint32_t* b) {
    asm volatile(
        "mma.sync.aligned.m16n8k8.row.col.f32.tf32.tf32.f32 "
        "{%0,%1,%2,%3}, {%4,%5,%6,%7}, {%8,%9}, {%0,%1,%2,%3};"
        : "+f"(c[0]), "+f"(c[1]), "+f"(c[2]), "+f"(c[3])
        : "r"(a[0]), "r"(a[1]), "r"(a[2]), "r"(a[3]), "r"(b[0]), "r"(b[1]));
}

// ===========================================================================
// Unified tf32 mma GEMM: C[z] = A[z] (MxK) @ B[z] (KxN), row-major.
// Block 128x128, BK=32, 8 warps (warp tile 32x64), cp.async double-buffered.
// ROUND_FRAGS: operands are raw fp32 -> +0x1000 rna trick at frag load.
// OUT_RNA: round epilogue stores to tf32 (for Wh feeding the next mma GEMM).
// SCALE_ELU: multiply row-scale then ELU (gemm2 epilogue).
// ===========================================================================
#define BM 128
#define BN 128
#define BK 32
#define APADF 36     // As[m][k] pad: bank = (4m + k) % 32, conflict-free
#define BPADF 136    // Bs[k][n] pad: bank = (8k + n) % 32, conflict-free
#define A_TILE_F (BM * APADF)            // 4608 floats
#define B_TILE_F (BK * BPADF)            // 4352 floats
#define STAGE_F (A_TILE_F + B_TILE_F)    // 8960 floats
#define GEMM_SMEM (2 * STAGE_F * 4)      // 71680 bytes

template <bool ROUND_FRAGS, bool OUT_RNA, bool SCALE_ELU>
__global__ __launch_bounds__(256, 2)
void gemm_tf32(const float* __restrict__ A, const float* __restrict__ B,
               float* __restrict__ C, const float* __restrict__ rowscale,
               int K, int ldA, int ldB, int ldC,
               size_t sA, size_t sB, size_t sC)
{
    extern __shared__ float smf[];
    const uint32_t sbase = smem_u32(smf);
    __shared__ float sInv[BM];

    const int tid = threadIdx.x;
    const int wid = tid >> 5;
    const int lane = tid & 31;
    const int wm = wid & 3;              // 4 warp rows of 32
    const int wn = wid >> 2;             // 2 warp cols of 64
    const int qid = lane >> 2;           // 0..7
    const int qtr = lane & 3;            // 0..3

    const float* Az = A + (size_t)blockIdx.z * sA + (size_t)(blockIdx.y * BM) * ldA;
    const float* Bz = B + (size_t)blockIdx.z * sB + blockIdx.x * BN;
    float* Cz = C + (size_t)blockIdx.z * sC;

    if (SCALE_ELU && tid < BM)
        sInv[tid] = rowscale[blockIdx.z * NN + blockIdx.y * BM + tid];

    float acc[2][8][4];
#pragma unroll
    for (int i = 0; i < 2; i++)
#pragma unroll
        for (int j = 0; j < 8; j++)
#pragma unroll
            for (int c = 0; c < 4; c++) acc[i][j][c] = 0.f;

    auto issue_tile = [&](int t, int stage) {
        const float* Aa = Az + t * BK;
        const float* Ba = Bz + (size_t)(t * BK) * ldB;
        const uint32_t abase = sbase + stage * (STAGE_F * 4);
        const uint32_t bbase = abase + A_TILE_F * 4;
#pragma unroll
        for (int l = 0; l < 4; l++) {
            int idx = tid + l * 256;
            int r = idx >> 3, kc = idx & 7;
            cp16(abase + (uint32_t)(r * APADF + kc * 4) * 4,
                 Aa + (size_t)r * ldA + kc * 4);
        }
#pragma unroll
        for (int l = 0; l < 4; l++) {
            int idx = tid + l * 256;
            int kr = idx >> 5, nc = idx & 31;
            cp16(bbase + (uint32_t)(kr * BPADF + nc * 4) * 4,
                 Ba + (size_t)kr * ldB + nc * 4);
        }
        asm volatile("cp.async.commit_group;" ::: "memory");
    };

    const int T = K / BK;
    issue_tile(0, 0);

    for (int t = 0; t < T; t++) {
        const int cur = t & 1;
        if (t + 1 < T) {
            issue_tile(t + 1, cur ^ 1);
            asm volatile("cp.async.wait_group 1;" ::: "memory");
        } else {
            asm volatile("cp.async.wait_group 0;" ::: "memory");
        }
        __syncthreads();

        const uint32_t* As = (const uint32_t*)smf + cur * STAGE_F;
        const uint32_t* Bs = As + A_TILE_F;

#pragma unroll
        for (int kk = 0; kk < BK / 8; kk++) {
            const int kb = kk * 8;
            uint32_t af[2][4];
#pragma unroll
            for (int mf = 0; mf < 2; mf++) {
                int mrow = wm * 32 + mf * 16 + qid;
                af[mf][0] = As[mrow * APADF + kb + qtr];
                af[mf][1] = As[(mrow + 8) * APADF + kb + qtr];
                af[mf][2] = As[mrow * APADF + kb + qtr + 4];
                af[mf][3] = As[(mrow + 8) * APADF + kb + qtr + 4];
                if (ROUND_FRAGS) {
                    af[mf][0] += 0x1000u; af[mf][1] += 0x1000u;
                    af[mf][2] += 0x1000u; af[mf][3] += 0x1000u;
                }
            }
            uint32_t bf[8][2];
#pragma unroll
            for (int nf = 0; nf < 8; nf++) {
                int ncol = wn * 64 + nf * 8 + qid;
                bf[nf][0] = Bs[(kb + qtr) * BPADF + ncol];
                bf[nf][1] = Bs[(kb + qtr + 4) * BPADF + ncol];
                if (ROUND_FRAGS) {
                    bf[nf][0] += 0x1000u; bf[nf][1] += 0x1000u;
                }
            }
#pragma unroll
            for (int mf = 0; mf < 2; mf++)
#pragma unroll
                for (int nf = 0; nf < 8; nf++)
                    mma_tf32(acc[mf][nf], af[mf], bf[nf]);
        }
        __syncthreads();
    }

    // Epilogue. c0,c1 -> row qid; c2,c3 -> row qid+8.
    const int row_base = blockIdx.y * BM + wm * 32;
    const int col_base = blockIdx.x * BN + wn * 64;
#pragma unroll
    for (int mf = 0; mf < 2; mf++) {
#pragma unroll
        for (int half = 0; half < 2; half++) {
            int rloc = wm * 32 + mf * 16 + qid + half * 8;
            int r = blockIdx.y * BM + rloc;
            float* crow = Cz + (size_t)r * ldC;
            float scale = SCALE_ELU ? sInv[rloc] : 1.0f;
#pragma unroll
            for (int nf = 0; nf < 8; nf++) {
                float x0 = acc[mf][nf][half * 2];
                float x1 = acc[mf][nf][half * 2 + 1];
                float2 v;
                if (SCALE_ELU) {
                    x0 *= scale; x1 *= scale;
                    v.x = x0 > 0.f ? x0 : expm1f(x0);
                    v.y = x1 > 0.f ? x1 : expm1f(x1);
                } else if (OUT_RNA) {
                    v.x = rna_tf32(x0);
                    v.y = rna_tf32(x1);
                } else {
                    v.x = x0; v.y = x1;
                }
                *(float2*)(crow + col_base + nf * 8 + qtr * 2) = v;
            }
        }
    }
    (void)row_base;
}

// ---------------------------------------------------------------------------
// u1 = W @ a1, u2 = W @ a2  (one block per f, 256 threads over o; fp32)
// ---------------------------------------------------------------------------
__global__ __launch_bounds__(256)
void ukern(const float* __restrict__ W, const float* __restrict__ a,
           float* __restrict__ u)
{
    int f = blockIdx.x;
    int o = threadIdx.x;
    float w = W[f * FF + o];
    float s1 = w * a[o];
    float s2 = w * a[FF + o];
#pragma unroll
    for (int off = 16; off > 0; off >>= 1) {
        s1 += __shfl_down_sync(0xffffffffu, s1, off);
        s2 += __shfl_down_sync(0xffffffffu, s2, off);
    }
    __shared__ float sh1[8], sh2[8];
    int warp = o >> 5, lane = o & 31;
    if (lane == 0) { sh1[warp] = s1; sh2[warp] = s2; }
    __syncthreads();
    if (o == 0) {
        float t1 = 0.f, t2 = 0.f;
#pragma unroll
        for (int w2 = 0; w2 < 8; w2++) { t1 += sh1[w2]; t2 += sh2[w2]; }
        u[f] = t1;
        u[FF + f] = t2;
    }
}

// ---------------------------------------------------------------------------
// f1[r] = h_row . u1, f2[r] = h_row . u2   (fp32 — logits stay exact)
// ---------------------------------------------------------------------------
__global__ __launch_bounds__(256)
void fkern2(const float* __restrict__ h, const float* __restrict__ u,
            float* __restrict__ f1, float* __restrict__ f2)
{
    int row = blockIdx.x;
    int t = threadIdx.x;
    float hv = h[(size_t)row * FF + t];
    float s1 = hv * u[t];
    float s2 = hv * u[FF + t];
#pragma unroll
    for (int o = 16; o > 0; o >>= 1) {
        s1 += __shfl_down_sync(0xffffffffu, s1, o);
        s2 += __shfl_down_sync(0xffffffffu, s2, o);
    }
    __shared__ float sh1[8], sh2[8];
    int warp = t >> 5, lane = t & 31;
    if (lane == 0) { sh1[warp] = s1; sh2[warp] = s2; }
    __syncthreads();
    if (t == 0) {
        float t1 = 0.f, t2 = 0.f;
#pragma unroll
        for (int w2 = 0; w2 < 8; w2++) { t1 += sh1[w2]; t2 += sh2[w2]; }
        f1[row] = t1;
        f2[row] = t2;
    }
}

// ---------------------------------------------------------------------------
// Single-pass masked exp (no max subtraction — logits are small, masked
// entries are exact 0, softmax is shift-invariant). Writes UNNORMALIZED
// p = exp(leaky(f1+f2)) rounded to tf32, and invden[row] = 1/sum.
// The 1/sum scale is applied in gemm2's epilogue.
// One block per row; 256 threads x 4 j each (int4 / float4).
// ---------------------------------------------------------------------------
__global__ __launch_bounds__(256)
void attn_p(const int* __restrict__ adj, float* __restrict__ P,
            const float* __restrict__ f1, const float* __restrict__ f2,
            float* __restrict__ invden)
{
    const int row = blockIdx.x;           // b*N + i
    const int t = threadIdx.x;
    const int b = row >> 10;
    const float f1v = __ldg(f1 + row);

    int4 av = ((const int4*)(adj + (size_t)row * NN))[t];
    float4 f2v = ((const float4*)(f2 + ((size_t)b << 10)))[t];

    float s, e;
    s = f1v + f2v.x; e = s >= 0.f ? s : ALPHA * s;
    float p0 = (av.x > 0) ? __expf(e) : 0.f;
    s = f1v + f2v.y; e = s >= 0.f ? s : ALPHA * s;
    float p1 = (av.y > 0) ? __expf(e) : 0.f;
    s = f1v + f2v.z; e = s >= 0.f ? s : ALPHA * s;
    float p2 = (av.z > 0) ? __expf(e) : 0.f;
    s = f1v + f2v.w; e = s >= 0.f ? s : ALPHA * s;
    float p3 = (av.w > 0) ? __expf(e) : 0.f;

    float4 st;
    st.x = rna_tf32(p0); st.y = rna_tf32(p1);
    st.z = rna_tf32(p2); st.w = rna_tf32(p3);
    ((float4*)(P + (size_t)row * NN))[t] = st;

    float sum = (p0 + p1) + (p2 + p3);
#pragma unroll
    for (int o = 16; o > 0; o >>= 1)
        sum += __shfl_xor_sync(0xffffffffu, sum, o);

    __shared__ float red[8];
    int warp = t >> 5, lane = t & 31;
    if (lane == 0) red[warp] = sum;
    __syncthreads();
    if (t == 0) {
        float tot = 0.f;
#pragma unroll
        for (int w2 = 0; w2 < 8; w2++) tot += red[w2];
        invden[row] = 1.0f / tot;
    }
}

// ---------------------------------------------------------------------------
// Launch
// ---------------------------------------------------------------------------
extern "C" void kernel_launch(void* const* d_in, const int* in_sizes, int n_in,
                              void* d_out, int out_size)
{
    const float* h   = (const float*)d_in[0];   // [16,1024,256]
    const int*   adj = (const int*)d_in[1];     // [16,1024,1024]
    const float* W   = (const float*)d_in[2];   // [256,256]
    const float* a   = (const float*)d_in[3];   // [512,1]
    float* out = (float*)d_out;                 // [16,1024,256]

    float *Wh, *u, *f1, *f2, *P, *invden;
    cudaGetSymbolAddress((void**)&Wh,     g_Wh);
    cudaGetSymbolAddress((void**)&u,      g_u);
    cudaGetSymbolAddress((void**)&f1,     g_f1);
    cudaGetSymbolAddress((void**)&f2,     g_f2);
    cudaGetSymbolAddress((void**)&P,      g_P);
    cudaGetSymbolAddress((void**)&invden, g_invden);

    cudaFuncSetAttribute((const void*)gemm_tf32<true, true, false>,
                         cudaFuncAttributeMaxDynamicSharedMemorySize, GEMM_SMEM);
    cudaFuncSetAttribute((const void*)gemm_tf32<false, false, true>,
                         cudaFuncAttributeMaxDynamicSharedMemorySize, GEMM_SMEM);

    // 1) u1,u2 = W@a1, W@a2 (fp32)
    ukern<<<FF, 256>>>(W, a, u);

    // 2) f1,f2 = h@u1, h@u2 (fp32 — softmax logits exact)
    fkern2<<<BB * NN, 256>>>(h, u, f1, f2);

    // 3) Wh = h @ W  (tf32 mma; fragments rounded in-loop; output stored tf32-rna)
    gemm_tf32<true, true, false><<<dim3(FF / BN, (BB * NN) / BM, 1), 256, GEMM_SMEM>>>(
        h, W, Wh, nullptr, FF, FF, FF, FF, 0, 0, 0);

    // 4) single-pass masked exp -> unnormalized P + invden
    attn_p<<<BB * NN, 256>>>(adj, P, f1, f2, invden);

    // 5) out = elu( invden * (P @ Wh) )  (tf32 mma; pre-rounded operands)
    gemm_tf32<false, false, true><<<dim3(FF / BN, NN / BM, BB), 256, GEMM_SMEM>>>(
        P, Wh, out, invden, NN, NN, FF, FF,
        (size_t)NN * NN, (size_t)NN * FF, (size_t)NN * FF);
}

// round 11
// speedup vs baseline: 3.5269x; 1.4156x over previous
#include <cuda_runtime.h>
#include <cuda_fp16.h>
#include <math.h>
#include <stdint.h>

// Problem constants
#define BB 16
#define NN 1024
#define FF 256
#define ALPHA 0.2f

// Scratch (device globals — no allocations allowed)
__device__ __half g_WhT[(size_t)BB * FF * NN];      // 8 MB  [b][o][j] fp16
__device__ float g_u[2 * FF];                       // u1 = W@a1, u2 = W@a2
__device__ float g_f1[BB * NN];
__device__ float g_f2[BB * NN];
__device__ float g_maxf2[BB];
__device__ __half g_P[(size_t)BB * NN * NN];        // 32 MB shifted exp, fp16
__device__ float g_invden[BB * NN];                 // 1 / row sum (of shifted exps)

// ---------------------------------------------------------------------------
// Helpers
// ---------------------------------------------------------------------------
__device__ __forceinline__ void cp16(uint32_t saddr, const void* gptr) {
    asm volatile("cp.async.cg.shared.global [%0], [%1], 16;"
                 :: "r"(saddr), "l"(gptr) : "memory");
}

__device__ __forceinline__ uint32_t smem_u32(const void* p) {
    uint32_t a;
    asm("{ .reg .u64 t; cvta.to.shared.u64 t, %1; cvt.u32.u64 %0, t; }"
        : "=r"(a) : "l"(p));
    return a;
}

__device__ __forceinline__ void mma_tf32(float* c, const uint32_t* a, const uint32_t* b) {
    asm volatile(
        "mma.sync.aligned.m16n8k8.row.col.f32.tf32.tf32.f32 "
        "{%0,%1,%2,%3}, {%4,%5,%6,%7}, {%8,%9}, {%0,%1,%2,%3};"
        : "+f"(c[0]), "+f"(c[1]), "+f"(c[2]), "+f"(c[3])
        : "r"(a[0]), "r"(a[1]), "r"(a[2]), "r"(a[3]), "r"(b[0]), "r"(b[1]));
}

__device__ __forceinline__ void mma_f16(float* c, const uint32_t* a, const uint32_t* b) {
    asm volatile(
        "mma.sync.aligned.m16n8k16.row.col.f32.f16.f16.f32 "
        "{%0,%1,%2,%3}, {%4,%5,%6,%7}, {%8,%9}, {%0,%1,%2,%3};"
        : "+f"(c[0]), "+f"(c[1]), "+f"(c[2]), "+f"(c[3])
        : "r"(a[0]), "r"(a[1]), "r"(a[2]), "r"(a[3]), "r"(b[0]), "r"(b[1]));
}

// ===========================================================================
// GEMM1 (tf32): WhT[b][o][j] (fp16) = (h[b*N+j][f] @ W[f][o])^T
// Block 128x128, BK=32, 2-stage cp.async (proven skeleton).
// ===========================================================================
#define BM 128
#define BN 128
#define BK1 32
#define APADF 36
#define BPADF 136
#define A1_TILE_F (BM * APADF)
#define B1_TILE_F (BK1 * BPADF)
#define STAGE1_F (A1_TILE_F + B1_TILE_F)
#define G1_SMEM (2 * STAGE1_F * 4)

__global__ __launch_bounds__(256, 2)
void gemm1_tf32(const float* __restrict__ A, const float* __restrict__ B,
                __half* __restrict__ WhT)
{
    extern __shared__ float smf[];
    const uint32_t sbase = smem_u32(smf);

    const int tid = threadIdx.x;
    const int wid = tid >> 5;
    const int lane = tid & 31;
    const int wm = wid & 3;
    const int wn = wid >> 2;
    const int qid = lane >> 2;
    const int qtr = lane & 3;

    const float* Az = A + (size_t)(blockIdx.y * BM) * FF;
    const float* Bz = B + blockIdx.x * BN;

    float acc[2][8][4];
#pragma unroll
    for (int i = 0; i < 2; i++)
#pragma unroll
        for (int j = 0; j < 8; j++)
#pragma unroll
            for (int c = 0; c < 4; c++) acc[i][j][c] = 0.f;

    auto issue_tile = [&](int t, int stage) {
        const float* Aa = Az + t * BK1;
        const float* Ba = Bz + (size_t)(t * BK1) * FF;
        const uint32_t abase = sbase + stage * (STAGE1_F * 4);
        const uint32_t bbase = abase + A1_TILE_F * 4;
#pragma unroll
        for (int l = 0; l < 4; l++) {
            int idx = tid + l * 256;
            int r = idx >> 3, kc = idx & 7;
            cp16(abase + (uint32_t)(r * APADF + kc * 4) * 4,
                 Aa + (size_t)r * FF + kc * 4);
        }
#pragma unroll
        for (int l = 0; l < 4; l++) {
            int idx = tid + l * 256;
            int kr = idx >> 5, nc = idx & 31;
            cp16(bbase + (uint32_t)(kr * BPADF + nc * 4) * 4,
                 Ba + (size_t)kr * FF + nc * 4);
        }
        asm volatile("cp.async.commit_group;" ::: "memory");
    };

    const int T = FF / BK1;   // 8
    issue_tile(0, 0);

    for (int t = 0; t < T; t++) {
        const int cur = t & 1;
        if (t + 1 < T) {
            issue_tile(t + 1, cur ^ 1);
            asm volatile("cp.async.wait_group 1;" ::: "memory");
        } else {
            asm volatile("cp.async.wait_group 0;" ::: "memory");
        }
        __syncthreads();

        const uint32_t* As = (const uint32_t*)smf + cur * STAGE1_F;
        const uint32_t* Bs = As + A1_TILE_F;

#pragma unroll
        for (int kk = 0; kk < BK1 / 8; kk++) {
            const int kb = kk * 8;
            uint32_t af[2][4];
#pragma unroll
            for (int mf = 0; mf < 2; mf++) {
                int mrow = wm * 32 + mf * 16 + qid;
                af[mf][0] = As[mrow * APADF + kb + qtr] + 0x1000u;
                af[mf][1] = As[(mrow + 8) * APADF + kb + qtr] + 0x1000u;
                af[mf][2] = As[mrow * APADF + kb + qtr + 4] + 0x1000u;
                af[mf][3] = As[(mrow + 8) * APADF + kb + qtr + 4] + 0x1000u;
            }
            uint32_t bf[8][2];
#pragma unroll
            for (int nf = 0; nf < 8; nf++) {
                int ncol = wn * 64 + nf * 8 + qid;
                bf[nf][0] = Bs[(kb + qtr) * BPADF + ncol] + 0x1000u;
                bf[nf][1] = Bs[(kb + qtr + 4) * BPADF + ncol] + 0x1000u;
            }
#pragma unroll
            for (int mf = 0; mf < 2; mf++)
#pragma unroll
                for (int nf = 0; nf < 8; nf++)
                    mma_tf32(acc[mf][nf], af[mf], bf[nf]);
        }
        __syncthreads();
    }

    // Transposed fp16 epilogue: WhT[b][o][j], b = r>>10, j = r&1023
    const int col_base = blockIdx.x * BN + wn * 64;
#pragma unroll
    for (int mf = 0; mf < 2; mf++) {
#pragma unroll
        for (int half = 0; half < 2; half++) {
            int r = blockIdx.y * BM + wm * 32 + mf * 16 + qid + half * 8;
            int b = r >> 10, j = r & 1023;
            __half* base = WhT + (size_t)b * FF * NN + j;
#pragma unroll
            for (int nf = 0; nf < 8; nf++) {
                int o = col_base + nf * 8 + qtr * 2;
                base[(size_t)o * NN]       = __float2half_rn(acc[mf][nf][half * 2]);
                base[(size_t)(o + 1) * NN] = __float2half_rn(acc[mf][nf][half * 2 + 1]);
            }
        }
    }
}

// ===========================================================================
// GEMM2 (fp16): out[z] = elu( invden * ( P[z] (1024x1024 f16) @ WhT[z]^T ) )
// A = P [m][k] f16, B = WhT [n][k] f16 (n-major). Block 128x128, BK=64,
// 3-stage cp.async pipeline. (Structure proven in R10; format now fp16.)
// ===========================================================================
#define BK2 64
#define PADU 36                       // u32 row pitch (32 data + 4 pad)
#define A2_TILE_U (128 * PADU)
#define B2_TILE_U (128 * PADU)
#define STAGE2_U (A2_TILE_U + B2_TILE_U)    // 9216 u32 = 36864 B
#define G2_SMEM (3 * STAGE2_U * 4)          // 110592 B

__global__ __launch_bounds__(256, 2)
void gemm2_fp16(const __half* __restrict__ P,
                const __half* __restrict__ WhT,
                float* __restrict__ out, const float* __restrict__ invden)
{
    extern __shared__ float smf[];
    const uint32_t sbase = smem_u32(smf);
    __shared__ float sInv[BM];

    const int tid = threadIdx.x;
    const int wid = tid >> 5;
    const int lane = tid & 31;
    const int wm = wid & 3;
    const int wn = wid >> 2;
    const int qid = lane >> 2;
    const int qtr = lane & 3;

    const __half* Az = P + (size_t)blockIdx.z * NN * NN + (size_t)(blockIdx.y * BM) * NN;
    const __half* Bz = WhT + (size_t)blockIdx.z * FF * NN + (size_t)(blockIdx.x * BN) * NN;
    float* Cz = out + (size_t)blockIdx.z * NN * FF;

    if (tid < BM)
        sInv[tid] = invden[blockIdx.z * NN + blockIdx.y * BM + tid];

    float acc[2][8][4];
#pragma unroll
    for (int i = 0; i < 2; i++)
#pragma unroll
        for (int j = 0; j < 8; j++)
#pragma unroll
            for (int c = 0; c < 4; c++) acc[i][j][c] = 0.f;

    auto issue_tile = [&](int t, int stage) {
        const __half* Aa = Az + t * BK2;
        const __half* Ba = Bz + t * BK2;
        const uint32_t abase = sbase + stage * (STAGE2_U * 4);
        const uint32_t bbase = abase + A2_TILE_U * 4;
#pragma unroll
        for (int l = 0; l < 4; l++) {
            int idx = tid + l * 256;
            int r = idx >> 3, c = idx & 7;           // 8 chunks of 16B per 128B row
            cp16(abase + (uint32_t)(r * PADU * 4 + c * 16),
                 Aa + (size_t)r * NN + c * 8);
        }
#pragma unroll
        for (int l = 0; l < 4; l++) {
            int idx = tid + l * 256;
            int r = idx >> 3, c = idx & 7;
            cp16(bbase + (uint32_t)(r * PADU * 4 + c * 16),
                 Ba + (size_t)r * NN + c * 8);
        }
        asm volatile("cp.async.commit_group;" ::: "memory");
    };

    const int T = NN / BK2;   // 16
    issue_tile(0, 0);
    issue_tile(1, 1);

    for (int t = 0; t < T; t++) {
        if (t < T - 1) {
            asm volatile("cp.async.wait_group 1;" ::: "memory");
        } else {
            asm volatile("cp.async.wait_group 0;" ::: "memory");
        }
        __syncthreads();
        if (t + 2 < T) issue_tile(t + 2, (t + 2) % 3);

        const uint32_t* As = (const uint32_t*)smf + (t % 3) * STAGE2_U;
        const uint32_t* Bs = As + A2_TILE_U;

#pragma unroll
        for (int kk = 0; kk < 4; kk++) {          // 4 k-steps of 16
            const int kbu = kk * 8;               // u32 offset
            uint32_t af[2][4];
#pragma unroll
            for (int mf = 0; mf < 2; mf++) {
                int mrow = wm * 32 + mf * 16 + qid;
                af[mf][0] = As[mrow * PADU + kbu + qtr];
                af[mf][1] = As[(mrow + 8) * PADU + kbu + qtr];
                af[mf][2] = As[mrow * PADU + kbu + qtr + 4];
                af[mf][3] = As[(mrow + 8) * PADU + kbu + qtr + 4];
            }
            uint32_t bf[8][2];
#pragma unroll
            for (int nf = 0; nf < 8; nf++) {
                int ncol = wn * 64 + nf * 8 + qid;
                bf[nf][0] = Bs[ncol * PADU + kbu + qtr];
                bf[nf][1] = Bs[ncol * PADU + kbu + qtr + 4];
            }
#pragma unroll
            for (int mf = 0; mf < 2; mf++)
#pragma unroll
                for (int nf = 0; nf < 8; nf++)
                    mma_f16(acc[mf][nf], af[mf], bf[nf]);
        }
    }

    // Epilogue: scale by invden, ELU, store fp32.
    const int col_base = blockIdx.x * BN + wn * 64;
#pragma unroll
    for (int mf = 0; mf < 2; mf++) {
#pragma unroll
        for (int half = 0; half < 2; half++) {
            int rloc = wm * 32 + mf * 16 + qid + half * 8;
            int r = blockIdx.y * BM + rloc;
            float* crow = Cz + (size_t)r * FF;
            float scale = sInv[rloc];
#pragma unroll
            for (int nf = 0; nf < 8; nf++) {
                float x0 = acc[mf][nf][half * 2] * scale;
                float x1 = acc[mf][nf][half * 2 + 1] * scale;
                float2 v;
                v.x = x0 > 0.f ? x0 : expm1f(x0);
                v.y = x1 > 0.f ? x1 : expm1f(x1);
                *(float2*)(crow + col_base + nf * 8 + qtr * 2) = v;
            }
        }
    }
}

// ---------------------------------------------------------------------------
// u1 = W @ a1, u2 = W @ a2  (one block per f, 256 threads over o; fp32)
// ---------------------------------------------------------------------------
__global__ __launch_bounds__(256)
void ukern(const float* __restrict__ W, const float* __restrict__ a,
           float* __restrict__ u)
{
    int f = blockIdx.x;
    int o = threadIdx.x;
    float w = W[f * FF + o];
    float s1 = w * a[o];
    float s2 = w * a[FF + o];
#pragma unroll
    for (int off = 16; off > 0; off >>= 1) {
        s1 += __shfl_down_sync(0xffffffffu, s1, off);
        s2 += __shfl_down_sync(0xffffffffu, s2, off);
    }
    __shared__ float sh1[8], sh2[8];
    int warp = o >> 5, lane = o & 31;
    if (lane == 0) { sh1[warp] = s1; sh2[warp] = s2; }
    __syncthreads();
    if (o == 0) {
        float t1 = 0.f, t2 = 0.f;
#pragma unroll
        for (int w2 = 0; w2 < 8; w2++) { t1 += sh1[w2]; t2 += sh2[w2]; }
        u[f] = t1;
        u[FF + f] = t2;
    }
}

// ---------------------------------------------------------------------------
// fkern3: warp-per-row. f1[r] = h_row . u1, f2[r] = h_row . u2 (fp32 exact)
// grid = BB*NN/8 blocks of 256 threads (8 warps = 8 rows).
// ---------------------------------------------------------------------------
__global__ __launch_bounds__(256)
void fkern3(const float* __restrict__ h, const float* __restrict__ u,
            float* __restrict__ f1, float* __restrict__ f2)
{
    const int warp = threadIdx.x >> 5, lane = threadIdx.x & 31;
    const int row = blockIdx.x * 8 + warp;

    const float4* hp = (const float4*)(h + (size_t)row * FF) + lane * 2;
    float4 h0 = hp[0], h1 = hp[1];
    const float4* u1p = (const float4*)u + lane * 2;
    const float4* u2p = (const float4*)(u + FF) + lane * 2;
    float4 u10 = u1p[0], u11 = u1p[1];
    float4 u20 = u2p[0], u21 = u2p[1];

    float s1 = h0.x * u10.x + h0.y * u10.y + h0.z * u10.z + h0.w * u10.w
             + h1.x * u11.x + h1.y * u11.y + h1.z * u11.z + h1.w * u11.w;
    float s2 = h0.x * u20.x + h0.y * u20.y + h0.z * u20.z + h0.w * u20.w
             + h1.x * u21.x + h1.y * u21.y + h1.z * u21.z + h1.w * u21.w;
#pragma unroll
    for (int o = 16; o > 0; o >>= 1) {
        s1 += __shfl_xor_sync(0xffffffffu, s1, o);
        s2 += __shfl_xor_sync(0xffffffffu, s2, o);
    }
    if (lane == 0) { f1[row] = s1; f2[row] = s2; }
}

// ---------------------------------------------------------------------------
// Per-batch max of f2 (for the fp16-safe shift). One block per batch.
// ---------------------------------------------------------------------------
__global__ __launch_bounds__(256)
void maxf2kern(const float* __restrict__ f2, float* __restrict__ maxf2)
{
    const int b = blockIdx.x;
    const int t = threadIdx.x;
    float4 v = ((const float4*)(f2 + ((size_t)b << 10)))[t];
    float m = fmaxf(fmaxf(v.x, v.y), fmaxf(v.z, v.w));
#pragma unroll
    for (int o = 16; o > 0; o >>= 1)
        m = fmaxf(m, __shfl_xor_sync(0xffffffffu, m, o));
    __shared__ float red[8];
    int warp = t >> 5, lane = t & 31;
    if (lane == 0) red[warp] = m;
    __syncthreads();
    if (t == 0) {
        float mm = red[0];
#pragma unroll
        for (int w2 = 1; w2 < 8; w2++) mm = fmaxf(mm, red[w2]);
        maxf2[b] = mm;
    }
}

// ---------------------------------------------------------------------------
// Single-pass masked exp -> shifted fp16 P + invden.
// Shift M_i = leaky(f1_i + max_b f2) >= all row logits (leaky monotone), so
// p = exp(e - M) in (0,1] — fp16-safe. Softmax is shift-invariant; the 1/sum
// scale is applied in gemm2's epilogue. 2 rows/block, 8 elts/thread.
// ---------------------------------------------------------------------------
__global__ __launch_bounds__(256)
void attn_p(const int* __restrict__ adj, __half* __restrict__ P,
            const float* __restrict__ f1, const float* __restrict__ f2,
            const float* __restrict__ maxf2, float* __restrict__ invden)
{
    const int row0 = blockIdx.x * 2;
    const int rh = threadIdx.x >> 7;          // 0/1: which row
    const int t = threadIdx.x & 127;
    const int row = row0 + rh;
    const int b = row >> 10;
    const float f1v = __ldg(f1 + row);
    const float fm = f1v + __ldg(maxf2 + b);
    const float M = fm >= 0.f ? fm : ALPHA * fm;   // row upper bound

    const int4* ap = (const int4*)(adj + (size_t)row * NN) + t * 2;
    const float4* fp = (const float4*)(f2 + ((size_t)b << 10)) + t * 2;
    int4 av0 = ap[0], av1 = ap[1];
    float4 f20 = fp[0], f21 = fp[1];

    float p[8];
    {
        float s;
        s = f1v + f20.x; s = s >= 0.f ? s : ALPHA * s; p[0] = (av0.x > 0) ? __expf(s - M) : 0.f;
        s = f1v + f20.y; s = s >= 0.f ? s : ALPHA * s; p[1] = (av0.y > 0) ? __expf(s - M) : 0.f;
        s = f1v + f20.z; s = s >= 0.f ? s : ALPHA * s; p[2] = (av0.z > 0) ? __expf(s - M) : 0.f;
        s = f1v + f20.w; s = s >= 0.f ? s : ALPHA * s; p[3] = (av0.w > 0) ? __expf(s - M) : 0.f;
        s = f1v + f21.x; s = s >= 0.f ? s : ALPHA * s; p[4] = (av1.x > 0) ? __expf(s - M) : 0.f;
        s = f1v + f21.y; s = s >= 0.f ? s : ALPHA * s; p[5] = (av1.y > 0) ? __expf(s - M) : 0.f;
        s = f1v + f21.z; s = s >= 0.f ? s : ALPHA * s; p[6] = (av1.z > 0) ? __expf(s - M) : 0.f;
        s = f1v + f21.w; s = s >= 0.f ? s : ALPHA * s; p[7] = (av1.w > 0) ? __expf(s - M) : 0.f;
    }

    __half2 h0 = __floats2half2_rn(p[0], p[1]);
    __half2 h1 = __floats2half2_rn(p[2], p[3]);
    __half2 h2 = __floats2half2_rn(p[4], p[5]);
    __half2 h3 = __floats2half2_rn(p[6], p[7]);
    uint4 st;
    st.x = *(uint32_t*)&h0; st.y = *(uint32_t*)&h1;
    st.z = *(uint32_t*)&h2; st.w = *(uint32_t*)&h3;
    ((uint4*)(P + (size_t)row * NN))[t] = st;

    float sum = ((p[0] + p[1]) + (p[2] + p[3])) + ((p[4] + p[5]) + (p[6] + p[7]));
#pragma unroll
    for (int o = 16; o > 0; o >>= 1)
        sum += __shfl_xor_sync(0xffffffffu, sum, o);

    __shared__ float red[8];
    int warp = threadIdx.x >> 5, lane = threadIdx.x & 31;
    if (lane == 0) red[warp] = sum;
    __syncthreads();
    if (threadIdx.x < 2) {
        int base = threadIdx.x * 4;
        float tot = (red[base] + red[base + 1]) + (red[base + 2] + red[base + 3]);
        invden[row0 + threadIdx.x] = 1.0f / tot;
    }
}

// ---------------------------------------------------------------------------
// Launch
// ---------------------------------------------------------------------------
extern "C" void kernel_launch(void* const* d_in, const int* in_sizes, int n_in,
                              void* d_out, int out_size)
{
    const float* h   = (const float*)d_in[0];   // [16,1024,256]
    const int*   adj = (const int*)d_in[1];     // [16,1024,1024]
    const float* W   = (const float*)d_in[2];   // [256,256]
    const float* a   = (const float*)d_in[3];   // [512,1]
    float* out = (float*)d_out;                 // [16,1024,256]

    __half *WhT, *P;
    float *u, *f1, *f2, *maxf2, *invden;
    cudaGetSymbolAddress((void**)&WhT,    g_WhT);
    cudaGetSymbolAddress((void**)&u,      g_u);
    cudaGetSymbolAddress((void**)&f1,     g_f1);
    cudaGetSymbolAddress((void**)&f2,     g_f2);
    cudaGetSymbolAddress((void**)&maxf2,  g_maxf2);
    cudaGetSymbolAddress((void**)&P,      g_P);
    cudaGetSymbolAddress((void**)&invden, g_invden);

    cudaFuncSetAttribute((const void*)gemm1_tf32,
                         cudaFuncAttributeMaxDynamicSharedMemorySize, G1_SMEM);
    cudaFuncSetAttribute((const void*)gemm2_fp16,
                         cudaFuncAttributeMaxDynamicSharedMemorySize, G2_SMEM);

    // 1) u1,u2 = W@a1, W@a2 (fp32)
    ukern<<<FF, 256>>>(W, a, u);

    // 2) f1,f2 = h@u1, h@u2 (fp32, warp-per-row — softmax logits exact)
    fkern3<<<(BB * NN) / 8, 256>>>(h, u, f1, f2);

    // 3) per-batch max of f2 (fp16-safe shift)
    maxf2kern<<<BB, 256>>>(f2, maxf2);

    // 4) WhT = (h @ W)^T per batch, fp16 (tf32 mma, transposed epilogue)
    gemm1_tf32<<<dim3(FF / BN, (BB * NN) / BM, 1), 256, G1_SMEM>>>(h, W, WhT);

    // 5) single-pass masked shifted exp -> fp16 P + invden
    attn_p<<<(BB * NN) / 2, 256>>>(adj, P, f1, f2, maxf2, invden);

    // 6) out = elu( invden * (P @ Wh) )  (fp16 mma, 3-stage pipeline)
    gemm2_fp16<<<dim3(FF / BN, NN / BM, BB), 256, G2_SMEM>>>(P, WhT, out, invden);
}

// round 12
// speedup vs baseline: 3.7393x; 1.0602x over previous
#include <cuda_runtime.h>
#include <cuda_fp16.h>
#include <math.h>
#include <stdint.h>

// Problem constants
#define BB 16
#define NN 1024
#define FF 256
#define ALPHA 0.2f

// Scratch (device globals — no allocations allowed)
__device__ __half g_WhT[(size_t)BB * FF * NN];      // 8 MB  [b][o][j] fp16
__device__ float g_u[2 * FF];                       // u1 = W@a1, u2 = W@a2
__device__ float g_f1[BB * NN];
__device__ float g_f2[BB * NN];
__device__ float g_maxf2[BB];
__device__ __half g_P[(size_t)BB * NN * NN];        // 32 MB shifted exp, fp16
__device__ float g_invden[BB * NN];                 // 1 / row sum (of shifted exps)

// ---------------------------------------------------------------------------
// Helpers
// ---------------------------------------------------------------------------
__device__ __forceinline__ void cp16(uint32_t saddr, const void* gptr) {
    asm volatile("cp.async.cg.shared.global [%0], [%1], 16;"
                 :: "r"(saddr), "l"(gptr) : "memory");
}

__device__ __forceinline__ uint32_t smem_u32(const void* p) {
    uint32_t a;
    asm("{ .reg .u64 t; cvta.to.shared.u64 t, %1; cvt.u32.u64 %0, t; }"
        : "=r"(a) : "l"(p));
    return a;
}

__device__ __forceinline__ void mma_tf32(float* c, const uint32_t* a, const uint32_t* b) {
    asm volatile(
        "mma.sync.aligned.m16n8k8.row.col.f32.tf32.tf32.f32 "
        "{%0,%1,%2,%3}, {%4,%5,%6,%7}, {%8,%9}, {%0,%1,%2,%3};"
        : "+f"(c[0]), "+f"(c[1]), "+f"(c[2]), "+f"(c[3])
        : "r"(a[0]), "r"(a[1]), "r"(a[2]), "r"(a[3]), "r"(b[0]), "r"(b[1]));
}

__device__ __forceinline__ void mma_f16(float* c, const uint32_t* a, const uint32_t* b) {
    asm volatile(
        "mma.sync.aligned.m16n8k16.row.col.f32.f16.f16.f32 "
        "{%0,%1,%2,%3}, {%4,%5,%6,%7}, {%8,%9}, {%0,%1,%2,%3};"
        : "+f"(c[0]), "+f"(c[1]), "+f"(c[2]), "+f"(c[3])
        : "r"(a[0]), "r"(a[1]), "r"(a[2]), "r"(a[3]), "r"(b[0]), "r"(b[1]));
}

__device__ __forceinline__ void ldm_x4(uint32_t& d0, uint32_t& d1,
                                       uint32_t& d2, uint32_t& d3, uint32_t a) {
    asm volatile("ldmatrix.sync.aligned.m8n8.x4.shared.b16 {%0,%1,%2,%3}, [%4];"
                 : "=r"(d0), "=r"(d1), "=r"(d2), "=r"(d3) : "r"(a));
}

// ===========================================================================
// GEMM1 (tf32): WhT[b][o][j] (fp16) = (h[b*N+j][f] @ W[f][o])^T
// Block 128x128, BK=32, 2-stage cp.async. Epilogue transposes through SMEM
// then stores coalesced 16B lines (fixes 16x write amplification).
// ===========================================================================
#define BM 128
#define BN 128
#define BK1 32
#define APADF 36
#define BPADF 136
#define A1_TILE_F (BM * APADF)
#define B1_TILE_F (BK1 * BPADF)
#define STAGE1_F (A1_TILE_F + B1_TILE_F)
#define G1_SMEM (2 * STAGE1_F * 4)
#define TPITCH 136   // fp16 pitch of transpose buffer (16B-aligned rows)

__global__ __launch_bounds__(256, 2)
void gemm1_tf32(const float* __restrict__ A, const float* __restrict__ B,
                __half* __restrict__ WhT)
{
    extern __shared__ float smf[];
    const uint32_t sbase = smem_u32(smf);

    const int tid = threadIdx.x;
    const int wid = tid >> 5;
    const int lane = tid & 31;
    const int wm = wid & 3;
    const int wn = wid >> 2;
    const int qid = lane >> 2;
    const int qtr = lane & 3;

    const float* Az = A + (size_t)(blockIdx.y * BM) * FF;
    const float* Bz = B + blockIdx.x * BN;

    float acc[2][8][4];
#pragma unroll
    for (int i = 0; i < 2; i++)
#pragma unroll
        for (int j = 0; j < 8; j++)
#pragma unroll
            for (int c = 0; c < 4; c++) acc[i][j][c] = 0.f;

    auto issue_tile = [&](int t, int stage) {
        const float* Aa = Az + t * BK1;
        const float* Ba = Bz + (size_t)(t * BK1) * FF;
        const uint32_t abase = sbase + stage * (STAGE1_F * 4);
        const uint32_t bbase = abase + A1_TILE_F * 4;
#pragma unroll
        for (int l = 0; l < 4; l++) {
            int idx = tid + l * 256;
            int r = idx >> 3, kc = idx & 7;
            cp16(abase + (uint32_t)(r * APADF + kc * 4) * 4,
                 Aa + (size_t)r * FF + kc * 4);
        }
#pragma unroll
        for (int l = 0; l < 4; l++) {
            int idx = tid + l * 256;
            int kr = idx >> 5, nc = idx & 31;
            cp16(bbase + (uint32_t)(kr * BPADF + nc * 4) * 4,
                 Ba + (size_t)kr * FF + nc * 4);
        }
        asm volatile("cp.async.commit_group;" ::: "memory");
    };

    const int T = FF / BK1;   // 8
    issue_tile(0, 0);

    for (int t = 0; t < T; t++) {
        const int cur = t & 1;
        if (t + 1 < T) {
            issue_tile(t + 1, cur ^ 1);
            asm volatile("cp.async.wait_group 1;" ::: "memory");
        } else {
            asm volatile("cp.async.wait_group 0;" ::: "memory");
        }
        __syncthreads();

        const uint32_t* As = (const uint32_t*)smf + cur * STAGE1_F;
        const uint32_t* Bs = As + A1_TILE_F;

#pragma unroll
        for (int kk = 0; kk < BK1 / 8; kk++) {
            const int kb = kk * 8;
            uint32_t af[2][4];
#pragma unroll
            for (int mf = 0; mf < 2; mf++) {
                int mrow = wm * 32 + mf * 16 + qid;
                af[mf][0] = As[mrow * APADF + kb + qtr] + 0x1000u;
                af[mf][1] = As[(mrow + 8) * APADF + kb + qtr] + 0x1000u;
                af[mf][2] = As[mrow * APADF + kb + qtr + 4] + 0x1000u;
                af[mf][3] = As[(mrow + 8) * APADF + kb + qtr + 4] + 0x1000u;
            }
            uint32_t bf[8][2];
#pragma unroll
            for (int nf = 0; nf < 8; nf++) {
                int ncol = wn * 64 + nf * 8 + qid;
                bf[nf][0] = Bs[(kb + qtr) * BPADF + ncol] + 0x1000u;
                bf[nf][1] = Bs[(kb + qtr + 4) * BPADF + ncol] + 0x1000u;
            }
#pragma unroll
            for (int mf = 0; mf < 2; mf++)
#pragma unroll
                for (int nf = 0; nf < 8; nf++)
                    mma_tf32(acc[mf][nf], af[mf], bf[nf]);
        }
        __syncthreads();
    }

    // ---- Transpose via SMEM, then coalesced fp16 stores ----
    __half* S = (__half*)smf;    // [128 o][TPITCH j]
    const int ob = wn * 64;
#pragma unroll
    for (int mf = 0; mf < 2; mf++) {
#pragma unroll
        for (int half = 0; half < 2; half++) {
            int j_l = wm * 32 + mf * 16 + qid + half * 8;
#pragma unroll
            for (int nf = 0; nf < 8; nf++) {
                int o_l = ob + nf * 8 + qtr * 2;
                S[o_l * TPITCH + j_l]       = __float2half_rn(acc[mf][nf][half * 2]);
                S[(o_l + 1) * TPITCH + j_l] = __float2half_rn(acc[mf][nf][half * 2 + 1]);
            }
        }
    }
    __syncthreads();

    const int r0 = blockIdx.y * BM;
    const int b = r0 >> 10, j0 = r0 & 1023;
    __half* Wb = WhT + (size_t)b * FF * NN + j0;
#pragma unroll
    for (int it = 0; it < 8; it++) {
        int idx = tid + it * 256;          // 0..2047
        int o_l = idx >> 4, jc = idx & 15; // 128 rows x 16 chunks of 16B
        uint4 v = *(uint4*)&S[o_l * TPITCH + jc * 8];
        int o_g = blockIdx.x * BN + o_l;
        *(uint4*)&Wb[(size_t)o_g * NN + jc * 8] = v;
    }
}

// ===========================================================================
// GEMM2 (fp16): out[z] = elu( invden * ( P[z] (1024x1024 f16) @ WhT[z]^T ) )
// A = P [m][k] f16, B = WhT [n][k] f16 (n-major). Block 128x128, BK=64,
// 3-stage cp.async pipeline. Fragments loaded via ldmatrix.x4 (issue: 40->22
// per k-step vs scalar LDS).
// ===========================================================================
#define BK2 64
#define PADU 36                       // u32 row pitch (32 data + 4 pad)
#define A2_TILE_U (128 * PADU)
#define B2_TILE_U (128 * PADU)
#define STAGE2_U (A2_TILE_U + B2_TILE_U)    // 9216 u32 = 36864 B
#define G2_SMEM (3 * STAGE2_U * 4)          // 110592 B

__global__ __launch_bounds__(256, 2)
void gemm2_fp16(const __half* __restrict__ P,
                const __half* __restrict__ WhT,
                float* __restrict__ out, const float* __restrict__ invden)
{
    extern __shared__ float smf[];
    const uint32_t sbase = smem_u32(smf);
    __shared__ float sInv[BM];

    const int tid = threadIdx.x;
    const int wid = tid >> 5;
    const int lane = tid & 31;
    const int wm = wid & 3;
    const int wn = wid >> 2;
    const int qid = lane >> 2;
    const int qtr = lane & 3;

    // ldmatrix per-lane address components (bytes)
    const int jj = lane >> 3, rr = lane & 7;
    const uint32_t a_lane = (uint32_t)(((wm * 32 + (jj & 1) * 8 + rr) * PADU
                                        + (jj >> 1) * 4) * 4);
    const uint32_t b_lane = (uint32_t)(((wn * 64 + (jj >> 1) * 8 + rr) * PADU
                                        + (jj & 1) * 4) * 4);

    const __half* Az = P + (size_t)blockIdx.z * NN * NN + (size_t)(blockIdx.y * BM) * NN;
    const __half* Bz = WhT + (size_t)blockIdx.z * FF * NN + (size_t)(blockIdx.x * BN) * NN;
    float* Cz = out + (size_t)blockIdx.z * NN * FF;

    if (tid < BM)
        sInv[tid] = invden[blockIdx.z * NN + blockIdx.y * BM + tid];

    float acc[2][8][4];
#pragma unroll
    for (int i = 0; i < 2; i++)
#pragma unroll
        for (int j = 0; j < 8; j++)
#pragma unroll
            for (int c = 0; c < 4; c++) acc[i][j][c] = 0.f;

    auto issue_tile = [&](int t, int stage) {
        const __half* Aa = Az + t * BK2;
        const __half* Ba = Bz + t * BK2;
        const uint32_t abase = sbase + stage * (STAGE2_U * 4);
        const uint32_t bbase = abase + A2_TILE_U * 4;
#pragma unroll
        for (int l = 0; l < 4; l++) {
            int idx = tid + l * 256;
            int r = idx >> 3, c = idx & 7;           // 8 chunks of 16B per 128B row
            cp16(abase + (uint32_t)(r * PADU * 4 + c * 16),
                 Aa + (size_t)r * NN + c * 8);
        }
#pragma unroll
        for (int l = 0; l < 4; l++) {
            int idx = tid + l * 256;
            int r = idx >> 3, c = idx & 7;
            cp16(bbase + (uint32_t)(r * PADU * 4 + c * 16),
                 Ba + (size_t)r * NN + c * 8);
        }
        asm volatile("cp.async.commit_group;" ::: "memory");
    };

    const int T = NN / BK2;   // 16
    issue_tile(0, 0);
    issue_tile(1, 1);

    for (int t = 0; t < T; t++) {
        if (t < T - 1) {
            asm volatile("cp.async.wait_group 1;" ::: "memory");
        } else {
            asm volatile("cp.async.wait_group 0;" ::: "memory");
        }
        __syncthreads();
        if (t + 2 < T) issue_tile(t + 2, (t + 2) % 3);

        const uint32_t stage_b = sbase + (uint32_t)((t % 3) * (STAGE2_U * 4));
        const uint32_t As_b = stage_b;
        const uint32_t Bs_b = stage_b + A2_TILE_U * 4;

#pragma unroll
        for (int kk = 0; kk < 4; kk++) {          // 4 k-steps of 16
            const uint32_t kboff = (uint32_t)(kk * 8 * 4);   // bytes
            uint32_t af[2][4];
            ldm_x4(af[0][0], af[0][1], af[0][2], af[0][3], As_b + a_lane + kboff);
            ldm_x4(af[1][0], af[1][1], af[1][2], af[1][3],
                   As_b + a_lane + (uint32_t)(16 * PADU * 4) + kboff);
            uint32_t bf[8][2];
#pragma unroll
            for (int nfp = 0; nfp < 4; nfp++) {
                uint32_t d0, d1, d2, d3;
                ldm_x4(d0, d1, d2, d3,
                       Bs_b + b_lane + (uint32_t)(nfp * 16 * PADU * 4) + kboff);
                bf[nfp * 2][0] = d0;     bf[nfp * 2][1] = d1;
                bf[nfp * 2 + 1][0] = d2; bf[nfp * 2 + 1][1] = d3;
            }
#pragma unroll
            for (int mf = 0; mf < 2; mf++)
#pragma unroll
                for (int nf = 0; nf < 8; nf++)
                    mma_f16(acc[mf][nf], af[mf], bf[nf]);
        }
    }

    // Epilogue: scale by invden, ELU, store fp32.
    const int col_base = blockIdx.x * BN + wn * 64;
#pragma unroll
    for (int mf = 0; mf < 2; mf++) {
#pragma unroll
        for (int half = 0; half < 2; half++) {
            int rloc = wm * 32 + mf * 16 + qid + half * 8;
            int r = blockIdx.y * BM + rloc;
            float* crow = Cz + (size_t)r * FF;
            float scale = sInv[rloc];
#pragma unroll
            for (int nf = 0; nf < 8; nf++) {
                float x0 = acc[mf][nf][half * 2] * scale;
                float x1 = acc[mf][nf][half * 2 + 1] * scale;
                float2 v;
                v.x = x0 > 0.f ? x0 : expm1f(x0);
                v.y = x1 > 0.f ? x1 : expm1f(x1);
                *(float2*)(crow + col_base + nf * 8 + qtr * 2) = v;
            }
        }
    }
}

// ---------------------------------------------------------------------------
// u1 = W @ a1, u2 = W @ a2  (one block per f, 256 threads over o; fp32)
// ---------------------------------------------------------------------------
__global__ __launch_bounds__(256)
void ukern(const float* __restrict__ W, const float* __restrict__ a,
           float* __restrict__ u)
{
    int f = blockIdx.x;
    int o = threadIdx.x;
    float w = W[f * FF + o];
    float s1 = w * a[o];
    float s2 = w * a[FF + o];
#pragma unroll
    for (int off = 16; off > 0; off >>= 1) {
        s1 += __shfl_down_sync(0xffffffffu, s1, off);
        s2 += __shfl_down_sync(0xffffffffu, s2, off);
    }
    __shared__ float sh1[8], sh2[8];
    int warp = o >> 5, lane = o & 31;
    if (lane == 0) { sh1[warp] = s1; sh2[warp] = s2; }
    __syncthreads();
    if (o == 0) {
        float t1 = 0.f, t2 = 0.f;
#pragma unroll
        for (int w2 = 0; w2 < 8; w2++) { t1 += sh1[w2]; t2 += sh2[w2]; }
        u[f] = t1;
        u[FF + f] = t2;
    }
}

// ---------------------------------------------------------------------------
// fkern3: warp-per-row. f1[r] = h_row . u1, f2[r] = h_row . u2 (fp32 exact)
// ---------------------------------------------------------------------------
__global__ __launch_bounds__(256)
void fkern3(const float* __restrict__ h, const float* __restrict__ u,
            float* __restrict__ f1, float* __restrict__ f2)
{
    const int warp = threadIdx.x >> 5, lane = threadIdx.x & 31;
    const int row = blockIdx.x * 8 + warp;

    const float4* hp = (const float4*)(h + (size_t)row * FF) + lane * 2;
    float4 h0 = hp[0], h1 = hp[1];
    const float4* u1p = (const float4*)u + lane * 2;
    const float4* u2p = (const float4*)(u + FF) + lane * 2;
    float4 u10 = u1p[0], u11 = u1p[1];
    float4 u20 = u2p[0], u21 = u2p[1];

    float s1 = h0.x * u10.x + h0.y * u10.y + h0.z * u10.z + h0.w * u10.w
             + h1.x * u11.x + h1.y * u11.y + h1.z * u11.z + h1.w * u11.w;
    float s2 = h0.x * u20.x + h0.y * u20.y + h0.z * u20.z + h0.w * u20.w
             + h1.x * u21.x + h1.y * u21.y + h1.z * u21.z + h1.w * u21.w;
#pragma unroll
    for (int o = 16; o > 0; o >>= 1) {
        s1 += __shfl_xor_sync(0xffffffffu, s1, o);
        s2 += __shfl_xor_sync(0xffffffffu, s2, o);
    }
    if (lane == 0) { f1[row] = s1; f2[row] = s2; }
}

// ---------------------------------------------------------------------------
// Per-batch max of f2 (for the fp16-safe shift). One block per batch.
// ---------------------------------------------------------------------------
__global__ __launch_bounds__(256)
void maxf2kern(const float* __restrict__ f2, float* __restrict__ maxf2)
{
    const int b = blockIdx.x;
    const int t = threadIdx.x;
    float4 v = ((const float4*)(f2 + ((size_t)b << 10)))[t];
    float m = fmaxf(fmaxf(v.x, v.y), fmaxf(v.z, v.w));
#pragma unroll
    for (int o = 16; o > 0; o >>= 1)
        m = fmaxf(m, __shfl_xor_sync(0xffffffffu, m, o));
    __shared__ float red[8];
    int warp = t >> 5, lane = t & 31;
    if (lane == 0) red[warp] = m;
    __syncthreads();
    if (t == 0) {
        float mm = red[0];
#pragma unroll
        for (int w2 = 1; w2 < 8; w2++) mm = fmaxf(mm, red[w2]);
        maxf2[b] = mm;
    }
}

// ---------------------------------------------------------------------------
// Single-pass masked exp -> shifted fp16 P + invden. (proven R11)
// ---------------------------------------------------------------------------
__global__ __launch_bounds__(256)
void attn_p(const int* __restrict__ adj, __half* __restrict__ P,
            const float* __restrict__ f1, const float* __restrict__ f2,
            const float* __restrict__ maxf2, float* __restrict__ invden)
{
    const int row0 = blockIdx.x * 2;
    const int rh = threadIdx.x >> 7;          // 0/1: which row
    const int t = threadIdx.x & 127;
    const int row = row0 + rh;
    const int b = row >> 10;
    const float f1v = __ldg(f1 + row);
    const float fm = f1v + __ldg(maxf2 + b);
    const float M = fm >= 0.f ? fm : ALPHA * fm;   // row upper bound

    const int4* ap = (const int4*)(adj + (size_t)row * NN) + t * 2;
    const float4* fp = (const float4*)(f2 + ((size_t)b << 10)) + t * 2;
    int4 av0 = ap[0], av1 = ap[1];
    float4 f20 = fp[0], f21 = fp[1];

    float p[8];
    {
        float s;
        s = f1v + f20.x; s = s >= 0.f ? s : ALPHA * s; p[0] = (av0.x > 0) ? __expf(s - M) : 0.f;
        s = f1v + f20.y; s = s >= 0.f ? s : ALPHA * s; p[1] = (av0.y > 0) ? __expf(s - M) : 0.f;
        s = f1v + f20.z; s = s >= 0.f ? s : ALPHA * s; p[2] = (av0.z > 0) ? __expf(s - M) : 0.f;
        s = f1v + f20.w; s = s >= 0.f ? s : ALPHA * s; p[3] = (av0.w > 0) ? __expf(s - M) : 0.f;
        s = f1v + f21.x; s = s >= 0.f ? s : ALPHA * s; p[4] = (av1.x > 0) ? __expf(s - M) : 0.f;
        s = f1v + f21.y; s = s >= 0.f ? s : ALPHA * s; p[5] = (av1.y > 0) ? __expf(s - M) : 0.f;
        s = f1v + f21.z; s = s >= 0.f ? s : ALPHA * s; p[6] = (av1.z > 0) ? __expf(s - M) : 0.f;
        s = f1v + f21.w; s = s >= 0.f ? s : ALPHA * s; p[7] = (av1.w > 0) ? __expf(s - M) : 0.f;
    }

    __half2 h0 = __floats2half2_rn(p[0], p[1]);
    __half2 h1 = __floats2half2_rn(p[2], p[3]);
    __half2 h2 = __floats2half2_rn(p[4], p[5]);
    __half2 h3 = __floats2half2_rn(p[6], p[7]);
    uint4 st;
    st.x = *(uint32_t*)&h0; st.y = *(uint32_t*)&h1;
    st.z = *(uint32_t*)&h2; st.w = *(uint32_t*)&h3;
    ((uint4*)(P + (size_t)row * NN))[t] = st;

    float sum = ((p[0] + p[1]) + (p[2] + p[3])) + ((p[4] + p[5]) + (p[6] + p[7]));
#pragma unroll
    for (int o = 16; o > 0; o >>= 1)
        sum += __shfl_xor_sync(0xffffffffu, sum, o);

    __shared__ float red[8];
    int warp = threadIdx.x >> 5, lane = threadIdx.x & 31;
    if (lane == 0) red[warp] = sum;
    __syncthreads();
    if (threadIdx.x < 2) {
        int base = threadIdx.x * 4;
        float tot = (red[base] + red[base + 1]) + (red[base + 2] + red[base + 3]);
        invden[row0 + threadIdx.x] = 1.0f / tot;
    }
}

// ---------------------------------------------------------------------------
// Launch
// ---------------------------------------------------------------------------
extern "C" void kernel_launch(void* const* d_in, const int* in_sizes, int n_in,
                              void* d_out, int out_size)
{
    const float* h   = (const float*)d_in[0];   // [16,1024,256]
    const int*   adj = (const int*)d_in[1];     // [16,1024,1024]
    const float* W   = (const float*)d_in[2];   // [256,256]
    const float* a   = (const float*)d_in[3];   // [512,1]
    float* out = (float*)d_out;                 // [16,1024,256]

    __half *WhT, *P;
    float *u, *f1, *f2, *maxf2, *invden;
    cudaGetSymbolAddress((void**)&WhT,    g_WhT);
    cudaGetSymbolAddress((void**)&u,      g_u);
    cudaGetSymbolAddress((void**)&f1,     g_f1);
    cudaGetSymbolAddress((void**)&f2,     g_f2);
    cudaGetSymbolAddress((void**)&maxf2,  g_maxf2);
    cudaGetSymbolAddress((void**)&P,      g_P);
    cudaGetSymbolAddress((void**)&invden, g_invden);

    cudaFuncSetAttribute((const void*)gemm1_tf32,
                         cudaFuncAttributeMaxDynamicSharedMemorySize, G1_SMEM);
    cudaFuncSetAttribute((const void*)gemm2_fp16,
                         cudaFuncAttributeMaxDynamicSharedMemorySize, G2_SMEM);

    // 1) u1,u2 = W@a1, W@a2 (fp32)
    ukern<<<FF, 256>>>(W, a, u);

    // 2) f1,f2 = h@u1, h@u2 (fp32, warp-per-row — softmax logits exact)
    fkern3<<<(BB * NN) / 8, 256>>>(h, u, f1, f2);

    // 3) per-batch max of f2 (fp16-safe shift)
    maxf2kern<<<BB, 256>>>(f2, maxf2);

    // 4) WhT = (h @ W)^T per batch, fp16 (tf32 mma, SMEM-transposed epilogue)
    gemm1_tf32<<<dim3(FF / BN, (BB * NN) / BM, 1), 256, G1_SMEM>>>(h, W, WhT);

    // 5) single-pass masked shifted exp -> fp16 P + invden
    attn_p<<<(BB * NN) / 2, 256>>>(adj, P, f1, f2, maxf2, invden);

    // 6) out = elu( invden * (P @ Wh) )  (fp16 mma, ldmatrix, 3-stage pipeline)
    gemm2_fp16<<<dim3(FF / BN, NN / BM, BB), 256, G2_SMEM>>>(P, WhT, out, invden);
}

// round 13
// speedup vs baseline: 3.8693x; 1.0348x over previous
#include <cuda_runtime.h>
#include <cuda_fp16.h>
#include <math.h>
#include <stdint.h>

// Problem constants
#define BB 16
#define NN 1024
#define FF 256
#define ALPHA 0.2f

// Scratch (device globals — no allocations allowed)
__device__ __half g_h16[(size_t)BB * NN * FF];      // 8 MB  h in fp16
__device__ __half g_Wt16[FF * FF];                  // W^T fp16 [o][f]
__device__ __half g_WhT[(size_t)BB * FF * NN];      // 8 MB  [b][o][j] fp16
__device__ float g_u[2 * FF];                       // u1 = W@a1, u2 = W@a2
__device__ float g_f1[BB * NN];
__device__ float g_f2[BB * NN];
__device__ float g_maxf2[BB];
__device__ __half g_P[(size_t)BB * NN * NN];        // 32 MB shifted exp, fp16
__device__ float g_invden[BB * NN];                 // 1 / row sum (of shifted exps)

// ---------------------------------------------------------------------------
// Helpers
// ---------------------------------------------------------------------------
__device__ __forceinline__ void cp16(uint32_t saddr, const void* gptr) {
    asm volatile("cp.async.cg.shared.global [%0], [%1], 16;"
                 :: "r"(saddr), "l"(gptr) : "memory");
}

__device__ __forceinline__ uint32_t smem_u32(const void* p) {
    uint32_t a;
    asm("{ .reg .u64 t; cvta.to.shared.u64 t, %1; cvt.u32.u64 %0, t; }"
        : "=r"(a) : "l"(p));
    return a;
}

__device__ __forceinline__ void mma_f16(float* c, const uint32_t* a, const uint32_t* b) {
    asm volatile(
        "mma.sync.aligned.m16n8k16.row.col.f32.f16.f16.f32 "
        "{%0,%1,%2,%3}, {%4,%5,%6,%7}, {%8,%9}, {%0,%1,%2,%3};"
        : "+f"(c[0]), "+f"(c[1]), "+f"(c[2]), "+f"(c[3])
        : "r"(a[0]), "r"(a[1]), "r"(a[2]), "r"(a[3]), "r"(b[0]), "r"(b[1]));
}

__device__ __forceinline__ void ldm_x4(uint32_t& d0, uint32_t& d1,
                                       uint32_t& d2, uint32_t& d3, uint32_t a) {
    asm volatile("ldmatrix.sync.aligned.m8n8.x4.shared.b16 {%0,%1,%2,%3}, [%4];"
                 : "=r"(d0), "=r"(d1), "=r"(d2), "=r"(d3) : "r"(a));
}

// Shared tile geometry (both fp16 GEMMs)
#define BM 128
#define BN 128
#define BK2 64
#define PADU 36                       // u32 row pitch (32 data + 4 pad)
#define A2_TILE_U (128 * PADU)
#define B2_TILE_U (128 * PADU)
#define STAGE2_U (A2_TILE_U + B2_TILE_U)    // 9216 u32 = 36864 B
#define G2_SMEM (3 * STAGE2_U * 4)          // 110592 B
#define TPITCH 136   // fp16 pitch of transpose buffer (16B-aligned rows)

// ===========================================================================
// GEMM1 (fp16): WhT[b][o][j] = (h16 @ W)^T.  A = h16 [16384 x 256],
// B = Wt16 [256 o][256 f] (n-major). K=256 -> T=4 k-tiles of 64.
// Same proven structure as gemm2 (ldmatrix + 3-stage cp.async); epilogue
// transposes via SMEM then stores coalesced 16B lines.
// ===========================================================================
__global__ __launch_bounds__(256, 2)
void gemm1_fp16(const __half* __restrict__ A, const __half* __restrict__ B,
                __half* __restrict__ WhT)
{
    extern __shared__ float smf[];
    const uint32_t sbase = smem_u32(smf);

    const int tid = threadIdx.x;
    const int wid = tid >> 5;
    const int lane = tid & 31;
    const int wm = wid & 3;
    const int wn = wid >> 2;
    const int qid = lane >> 2;
    const int qtr = lane & 3;

    const int jj = lane >> 3, rr = lane & 7;
    const uint32_t a_lane = (uint32_t)(((wm * 32 + (jj & 1) * 8 + rr) * PADU
                                        + (jj >> 1) * 4) * 4);
    const uint32_t b_lane = (uint32_t)(((wn * 64 + (jj >> 1) * 8 + rr) * PADU
                                        + (jj & 1) * 4) * 4);

    const __half* Az = A + (size_t)(blockIdx.y * BM) * FF;
    const __half* Bz = B + (size_t)(blockIdx.x * BN) * FF;

    float acc[2][8][4];
#pragma unroll
    for (int i = 0; i < 2; i++)
#pragma unroll
        for (int j = 0; j < 8; j++)
#pragma unroll
            for (int c = 0; c < 4; c++) acc[i][j][c] = 0.f;

    auto issue_tile = [&](int t, int stage) {
        const __half* Aa = Az + t * BK2;
        const __half* Ba = Bz + t * BK2;
        const uint32_t abase = sbase + stage * (STAGE2_U * 4);
        const uint32_t bbase = abase + A2_TILE_U * 4;
#pragma unroll
        for (int l = 0; l < 4; l++) {
            int idx = tid + l * 256;
            int r = idx >> 3, c = idx & 7;
            cp16(abase + (uint32_t)(r * PADU * 4 + c * 16),
                 Aa + (size_t)r * FF + c * 8);
        }
#pragma unroll
        for (int l = 0; l < 4; l++) {
            int idx = tid + l * 256;
            int r = idx >> 3, c = idx & 7;
            cp16(bbase + (uint32_t)(r * PADU * 4 + c * 16),
                 Ba + (size_t)r * FF + c * 8);
        }
        asm volatile("cp.async.commit_group;" ::: "memory");
    };

    const int T = FF / BK2;   // 4
    issue_tile(0, 0);
    issue_tile(1, 1);

    for (int t = 0; t < T; t++) {
        if (t < T - 1) {
            asm volatile("cp.async.wait_group 1;" ::: "memory");
        } else {
            asm volatile("cp.async.wait_group 0;" ::: "memory");
        }
        __syncthreads();
        if (t + 2 < T) issue_tile(t + 2, (t + 2) % 3);

        const uint32_t stage_b = sbase + (uint32_t)((t % 3) * (STAGE2_U * 4));
        const uint32_t As_b = stage_b;
        const uint32_t Bs_b = stage_b + A2_TILE_U * 4;

#pragma unroll
        for (int kk = 0; kk < 4; kk++) {
            const uint32_t kboff = (uint32_t)(kk * 8 * 4);
            uint32_t af[2][4];
            ldm_x4(af[0][0], af[0][1], af[0][2], af[0][3], As_b + a_lane + kboff);
            ldm_x4(af[1][0], af[1][1], af[1][2], af[1][3],
                   As_b + a_lane + (uint32_t)(16 * PADU * 4) + kboff);
            uint32_t bf[8][2];
#pragma unroll
            for (int nfp = 0; nfp < 4; nfp++) {
                uint32_t d0, d1, d2, d3;
                ldm_x4(d0, d1, d2, d3,
                       Bs_b + b_lane + (uint32_t)(nfp * 16 * PADU * 4) + kboff);
                bf[nfp * 2][0] = d0;     bf[nfp * 2][1] = d1;
                bf[nfp * 2 + 1][0] = d2; bf[nfp * 2 + 1][1] = d3;
            }
#pragma unroll
            for (int mf = 0; mf < 2; mf++)
#pragma unroll
                for (int nf = 0; nf < 8; nf++)
                    mma_f16(acc[mf][nf], af[mf], bf[nf]);
        }
    }

    // ---- Transpose via SMEM, then coalesced fp16 stores ----
    __syncthreads();   // smem stages no longer needed; reuse as transpose buf
    __half* S = (__half*)smf;    // [128 o][TPITCH j]
    const int ob = wn * 64;
#pragma unroll
    for (int mf = 0; mf < 2; mf++) {
#pragma unroll
        for (int half = 0; half < 2; half++) {
            int j_l = wm * 32 + mf * 16 + qid + half * 8;
#pragma unroll
            for (int nf = 0; nf < 8; nf++) {
                int o_l = ob + nf * 8 + qtr * 2;
                S[o_l * TPITCH + j_l]       = __float2half_rn(acc[mf][nf][half * 2]);
                S[(o_l + 1) * TPITCH + j_l] = __float2half_rn(acc[mf][nf][half * 2 + 1]);
            }
        }
    }
    __syncthreads();

    const int r0 = blockIdx.y * BM;
    const int b = r0 >> 10, j0 = r0 & 1023;
    __half* Wb = WhT + (size_t)b * FF * NN + j0;
#pragma unroll
    for (int it = 0; it < 8; it++) {
        int idx = tid + it * 256;          // 0..2047
        int o_l = idx >> 4, jc = idx & 15; // 128 rows x 16 chunks of 16B
        uint4 v = *(uint4*)&S[o_l * TPITCH + jc * 8];
        int o_g = blockIdx.x * BN + o_l;
        *(uint4*)&Wb[(size_t)o_g * NN + jc * 8] = v;
    }
}

// ===========================================================================
// GEMM2 (fp16): out[z] = elu( invden * ( P[z] @ WhT[z]^T ) )  (proven R12)
// ===========================================================================
__global__ __launch_bounds__(256, 2)
void gemm2_fp16(const __half* __restrict__ P,
                const __half* __restrict__ WhT,
                float* __restrict__ out, const float* __restrict__ invden)
{
    extern __shared__ float smf[];
    const uint32_t sbase = smem_u32(smf);
    __shared__ float sInv[BM];

    const int tid = threadIdx.x;
    const int wid = tid >> 5;
    const int lane = tid & 31;
    const int wm = wid & 3;
    const int wn = wid >> 2;
    const int qid = lane >> 2;
    const int qtr = lane & 3;

    const int jj = lane >> 3, rr = lane & 7;
    const uint32_t a_lane = (uint32_t)(((wm * 32 + (jj & 1) * 8 + rr) * PADU
                                        + (jj >> 1) * 4) * 4);
    const uint32_t b_lane = (uint32_t)(((wn * 64 + (jj >> 1) * 8 + rr) * PADU
                                        + (jj & 1) * 4) * 4);

    const __half* Az = P + (size_t)blockIdx.z * NN * NN + (size_t)(blockIdx.y * BM) * NN;
    const __half* Bz = WhT + (size_t)blockIdx.z * FF * NN + (size_t)(blockIdx.x * BN) * NN;
    float* Cz = out + (size_t)blockIdx.z * NN * FF;

    if (tid < BM)
        sInv[tid] = invden[blockIdx.z * NN + blockIdx.y * BM + tid];

    float acc[2][8][4];
#pragma unroll
    for (int i = 0; i < 2; i++)
#pragma unroll
        for (int j = 0; j < 8; j++)
#pragma unroll
            for (int c = 0; c < 4; c++) acc[i][j][c] = 0.f;

    auto issue_tile = [&](int t, int stage) {
        const __half* Aa = Az + t * BK2;
        const __half* Ba = Bz + t * BK2;
        const uint32_t abase = sbase + stage * (STAGE2_U * 4);
        const uint32_t bbase = abase + A2_TILE_U * 4;
#pragma unroll
        for (int l = 0; l < 4; l++) {
            int idx = tid + l * 256;
            int r = idx >> 3, c = idx & 7;
            cp16(abase + (uint32_t)(r * PADU * 4 + c * 16),
                 Aa + (size_t)r * NN + c * 8);
        }
#pragma unroll
        for (int l = 0; l < 4; l++) {
            int idx = tid + l * 256;
            int r = idx >> 3, c = idx & 7;
            cp16(bbase + (uint32_t)(r * PADU * 4 + c * 16),
                 Ba + (size_t)r * NN + c * 8);
        }
        asm volatile("cp.async.commit_group;" ::: "memory");
    };

    const int T = NN / BK2;   // 16
    issue_tile(0, 0);
    issue_tile(1, 1);

    for (int t = 0; t < T; t++) {
        if (t < T - 1) {
            asm volatile("cp.async.wait_group 1;" ::: "memory");
        } else {
            asm volatile("cp.async.wait_group 0;" ::: "memory");
        }
        __syncthreads();
        if (t + 2 < T) issue_tile(t + 2, (t + 2) % 3);

        const uint32_t stage_b = sbase + (uint32_t)((t % 3) * (STAGE2_U * 4));
        const uint32_t As_b = stage_b;
        const uint32_t Bs_b = stage_b + A2_TILE_U * 4;

#pragma unroll
        for (int kk = 0; kk < 4; kk++) {
            const uint32_t kboff = (uint32_t)(kk * 8 * 4);
            uint32_t af[2][4];
            ldm_x4(af[0][0], af[0][1], af[0][2], af[0][3], As_b + a_lane + kboff);
            ldm_x4(af[1][0], af[1][1], af[1][2], af[1][3],
                   As_b + a_lane + (uint32_t)(16 * PADU * 4) + kboff);
            uint32_t bf[8][2];
#pragma unroll
            for (int nfp = 0; nfp < 4; nfp++) {
                uint32_t d0, d1, d2, d3;
                ldm_x4(d0, d1, d2, d3,
                       Bs_b + b_lane + (uint32_t)(nfp * 16 * PADU * 4) + kboff);
                bf[nfp * 2][0] = d0;     bf[nfp * 2][1] = d1;
                bf[nfp * 2 + 1][0] = d2; bf[nfp * 2 + 1][1] = d3;
            }
#pragma unroll
            for (int mf = 0; mf < 2; mf++)
#pragma unroll
                for (int nf = 0; nf < 8; nf++)
                    mma_f16(acc[mf][nf], af[mf], bf[nf]);
        }
    }

    // Epilogue: scale by invden, ELU, store fp32.
    const int col_base = blockIdx.x * BN + wn * 64;
#pragma unroll
    for (int mf = 0; mf < 2; mf++) {
#pragma unroll
        for (int half = 0; half < 2; half++) {
            int rloc = wm * 32 + mf * 16 + qid + half * 8;
            int r = blockIdx.y * BM + rloc;
            float* crow = Cz + (size_t)r * FF;
            float scale = sInv[rloc];
#pragma unroll
            for (int nf = 0; nf < 8; nf++) {
                float x0 = acc[mf][nf][half * 2] * scale;
                float x1 = acc[mf][nf][half * 2 + 1] * scale;
                float2 v;
                v.x = x0 > 0.f ? x0 : expm1f(x0);
                v.y = x1 > 0.f ? x1 : expm1f(x1);
                *(float2*)(crow + col_base + nf * 8 + qtr * 2) = v;
            }
        }
    }
}

// ---------------------------------------------------------------------------
// conv_h: h (fp32) -> h16 (fp16). 8 elems/thread, 16B stores.
// ---------------------------------------------------------------------------
__global__ __launch_bounds__(256)
void conv_h(const float* __restrict__ h, __half* __restrict__ h16)
{
    size_t base = ((size_t)blockIdx.x * 256 + threadIdx.x) * 8;
    float4 a = *(const float4*)(h + base);
    float4 b = *(const float4*)(h + base + 4);
    __half2 h0 = __floats2half2_rn(a.x, a.y);
    __half2 h1 = __floats2half2_rn(a.z, a.w);
    __half2 h2 = __floats2half2_rn(b.x, b.y);
    __half2 h3 = __floats2half2_rn(b.z, b.w);
    uint4 st;
    st.x = *(uint32_t*)&h0; st.y = *(uint32_t*)&h1;
    st.z = *(uint32_t*)&h2; st.w = *(uint32_t*)&h3;
    *(uint4*)(h16 + base) = st;
}

// ---------------------------------------------------------------------------
// conv_wt: Wt16[o][f] = (half)W[f][o]. 32x32 smem tiles.
// ---------------------------------------------------------------------------
__global__ void conv_wt(const float* __restrict__ W, __half* __restrict__ Wt)
{
    __shared__ float t[32][33];
    int x = blockIdx.x * 32 + threadIdx.x;
#pragma unroll
    for (int i = 0; i < 4; i++) {
        int y = blockIdx.y * 32 + threadIdx.y + i * 8;
        t[threadIdx.y + i * 8][threadIdx.x] = W[y * FF + x];
    }
    __syncthreads();
#pragma unroll
    for (int i = 0; i < 4; i++) {
        int o = blockIdx.x * 32 + threadIdx.y + i * 8;
        int f = blockIdx.y * 32 + threadIdx.x;
        Wt[o * FF + f] = __float2half_rn(t[threadIdx.x][threadIdx.y + i * 8]);
    }
}

// ---------------------------------------------------------------------------
// u1 = W @ a1, u2 = W @ a2  (fp32)
// ---------------------------------------------------------------------------
__global__ __launch_bounds__(256)
void ukern(const float* __restrict__ W, const float* __restrict__ a,
           float* __restrict__ u)
{
    int f = blockIdx.x;
    int o = threadIdx.x;
    float w = W[f * FF + o];
    float s1 = w * a[o];
    float s2 = w * a[FF + o];
#pragma unroll
    for (int off = 16; off > 0; off >>= 1) {
        s1 += __shfl_down_sync(0xffffffffu, s1, off);
        s2 += __shfl_down_sync(0xffffffffu, s2, off);
    }
    __shared__ float sh1[8], sh2[8];
    int warp = o >> 5, lane = o & 31;
    if (lane == 0) { sh1[warp] = s1; sh2[warp] = s2; }
    __syncthreads();
    if (o == 0) {
        float t1 = 0.f, t2 = 0.f;
#pragma unroll
        for (int w2 = 0; w2 < 8; w2++) { t1 += sh1[w2]; t2 += sh2[w2]; }
        u[f] = t1;
        u[FF + f] = t2;
    }
}

// ---------------------------------------------------------------------------
// fkern3: warp-per-row. f1[r] = h_row . u1, f2[r] = h_row . u2 (fp32 exact)
// ---------------------------------------------------------------------------
__global__ __launch_bounds__(256)
void fkern3(const float* __restrict__ h, const float* __restrict__ u,
            float* __restrict__ f1, float* __restrict__ f2)
{
    const int warp = threadIdx.x >> 5, lane = threadIdx.x & 31;
    const int row = blockIdx.x * 8 + warp;

    const float4* hp = (const float4*)(h + (size_t)row * FF) + lane * 2;
    float4 h0 = hp[0], h1 = hp[1];
    const float4* u1p = (const float4*)u + lane * 2;
    const float4* u2p = (const float4*)(u + FF) + lane * 2;
    float4 u10 = u1p[0], u11 = u1p[1];
    float4 u20 = u2p[0], u21 = u2p[1];

    float s1 = h0.x * u10.x + h0.y * u10.y + h0.z * u10.z + h0.w * u10.w
             + h1.x * u11.x + h1.y * u11.y + h1.z * u11.z + h1.w * u11.w;
    float s2 = h0.x * u20.x + h0.y * u20.y + h0.z * u20.z + h0.w * u20.w
             + h1.x * u21.x + h1.y * u21.y + h1.z * u21.z + h1.w * u21.w;
#pragma unroll
    for (int o = 16; o > 0; o >>= 1) {
        s1 += __shfl_xor_sync(0xffffffffu, s1, o);
        s2 += __shfl_xor_sync(0xffffffffu, s2, o);
    }
    if (lane == 0) { f1[row] = s1; f2[row] = s2; }
}

// ---------------------------------------------------------------------------
// Per-batch max of f2 (fp16-safe shift). One block per batch.
// ---------------------------------------------------------------------------
__global__ __launch_bounds__(256)
void maxf2kern(const float* __restrict__ f2, float* __restrict__ maxf2)
{
    const int b = blockIdx.x;
    const int t = threadIdx.x;
    float4 v = ((const float4*)(f2 + ((size_t)b << 10)))[t];
    float m = fmaxf(fmaxf(v.x, v.y), fmaxf(v.z, v.w));
#pragma unroll
    for (int o = 16; o > 0; o >>= 1)
        m = fmaxf(m, __shfl_xor_sync(0xffffffffu, m, o));
    __shared__ float red[8];
    int warp = t >> 5, lane = t & 31;
    if (lane == 0) red[warp] = m;
    __syncthreads();
    if (t == 0) {
        float mm = red[0];
#pragma unroll
        for (int w2 = 1; w2 < 8; w2++) mm = fmaxf(mm, red[w2]);
        maxf2[b] = mm;
    }
}

// ---------------------------------------------------------------------------
// Single-pass masked exp -> shifted fp16 P + invden. (proven R11/R12)
// ---------------------------------------------------------------------------
__global__ __launch_bounds__(256)
void attn_p(const int* __restrict__ adj, __half* __restrict__ P,
            const float* __restrict__ f1, const float* __restrict__ f2,
            const float* __restrict__ maxf2, float* __restrict__ invden)
{
    const int row0 = blockIdx.x * 2;
    const int rh = threadIdx.x >> 7;          // 0/1: which row
    const int t = threadIdx.x & 127;
    const int row = row0 + rh;
    const int b = row >> 10;
    const float f1v = __ldg(f1 + row);
    const float fm = f1v + __ldg(maxf2 + b);
    const float M = fm >= 0.f ? fm : ALPHA * fm;   // row upper bound

    const int4* ap = (const int4*)(adj + (size_t)row * NN) + t * 2;
    const float4* fp = (const float4*)(f2 + ((size_t)b << 10)) + t * 2;
    int4 av0 = ap[0], av1 = ap[1];
    float4 f20 = fp[0], f21 = fp[1];

    float p[8];
    {
        float s;
        s = f1v + f20.x; s = s >= 0.f ? s : ALPHA * s; p[0] = (av0.x > 0) ? __expf(s - M) : 0.f;
        s = f1v + f20.y; s = s >= 0.f ? s : ALPHA * s; p[1] = (av0.y > 0) ? __expf(s - M) : 0.f;
        s = f1v + f20.z; s = s >= 0.f ? s : ALPHA * s; p[2] = (av0.z > 0) ? __expf(s - M) : 0.f;
        s = f1v + f20.w; s = s >= 0.f ? s : ALPHA * s; p[3] = (av0.w > 0) ? __expf(s - M) : 0.f;
        s = f1v + f21.x; s = s >= 0.f ? s : ALPHA * s; p[4] = (av1.x > 0) ? __expf(s - M) : 0.f;
        s = f1v + f21.y; s = s >= 0.f ? s : ALPHA * s; p[5] = (av1.y > 0) ? __expf(s - M) : 0.f;
        s = f1v + f21.z; s = s >= 0.f ? s : ALPHA * s; p[6] = (av1.z > 0) ? __expf(s - M) : 0.f;
        s = f1v + f21.w; s = s >= 0.f ? s : ALPHA * s; p[7] = (av1.w > 0) ? __expf(s - M) : 0.f;
    }

    __half2 h0 = __floats2half2_rn(p[0], p[1]);
    __half2 h1 = __floats2half2_rn(p[2], p[3]);
    __half2 h2 = __floats2half2_rn(p[4], p[5]);
    __half2 h3 = __floats2half2_rn(p[6], p[7]);
    uint4 st;
    st.x = *(uint32_t*)&h0; st.y = *(uint32_t*)&h1;
    st.z = *(uint32_t*)&h2; st.w = *(uint32_t*)&h3;
    ((uint4*)(P + (size_t)row * NN))[t] = st;

    float sum = ((p[0] + p[1]) + (p[2] + p[3])) + ((p[4] + p[5]) + (p[6] + p[7]));
#pragma unroll
    for (int o = 16; o > 0; o >>= 1)
        sum += __shfl_xor_sync(0xffffffffu, sum, o);

    __shared__ float red[8];
    int warp = threadIdx.x >> 5, lane = threadIdx.x & 31;
    if (lane == 0) red[warp] = sum;
    __syncthreads();
    if (threadIdx.x < 2) {
        int base = threadIdx.x * 4;
        float tot = (red[base] + red[base + 1]) + (red[base + 2] + red[base + 3]);
        invden[row0 + threadIdx.x] = 1.0f / tot;
    }
}

// ---------------------------------------------------------------------------
// Launch
// ---------------------------------------------------------------------------
extern "C" void kernel_launch(void* const* d_in, const int* in_sizes, int n_in,
                              void* d_out, int out_size)
{
    const float* h   = (const float*)d_in[0];   // [16,1024,256]
    const int*   adj = (const int*)d_in[1];     // [16,1024,1024]
    const float* W   = (const float*)d_in[2];   // [256,256]
    const float* a   = (const float*)d_in[3];   // [512,1]
    float* out = (float*)d_out;                 // [16,1024,256]

    __half *h16, *Wt16, *WhT, *P;
    float *u, *f1, *f2, *maxf2, *invden;
    cudaGetSymbolAddress((void**)&h16,    g_h16);
    cudaGetSymbolAddress((void**)&Wt16,   g_Wt16);
    cudaGetSymbolAddress((void**)&WhT,    g_WhT);
    cudaGetSymbolAddress((void**)&u,      g_u);
    cudaGetSymbolAddress((void**)&f1,     g_f1);
    cudaGetSymbolAddress((void**)&f2,     g_f2);
    cudaGetSymbolAddress((void**)&maxf2,  g_maxf2);
    cudaGetSymbolAddress((void**)&P,      g_P);
    cudaGetSymbolAddress((void**)&invden, g_invden);

    cudaFuncSetAttribute((const void*)gemm1_fp16,
                         cudaFuncAttributeMaxDynamicSharedMemorySize, G2_SMEM);
    cudaFuncSetAttribute((const void*)gemm2_fp16,
                         cudaFuncAttributeMaxDynamicSharedMemorySize, G2_SMEM);

    // 1) conversions: h -> fp16, W -> W^T fp16
    conv_h<<<(BB * NN * FF) / 2048, 256>>>(h, h16);
    conv_wt<<<dim3(8, 8), dim3(32, 8)>>>(W, Wt16);

    // 2) u1,u2 = W@a1, W@a2 (fp32)
    ukern<<<FF, 256>>>(W, a, u);

    // 3) f1,f2 = h@u1, h@u2 (fp32, warp-per-row — softmax logits exact)
    fkern3<<<(BB * NN) / 8, 256>>>(h, u, f1, f2);

    // 4) per-batch max of f2 (fp16-safe shift)
    maxf2kern<<<BB, 256>>>(f2, maxf2);

    // 5) WhT = (h16 @ W)^T per batch (fp16 mma, ldmatrix, SMEM-transposed)
    gemm1_fp16<<<dim3(FF / BN, (BB * NN) / BM, 1), 256, G2_SMEM>>>(h16, Wt16, WhT);

    // 6) single-pass masked shifted exp -> fp16 P + invden
    attn_p<<<(BB * NN) / 2, 256>>>(adj, P, f1, f2, maxf2, invden);

    // 7) out = elu( invden * (P @ Wh) )  (fp16 mma, ldmatrix, 3-stage pipeline)
    gemm2_fp16<<<dim3(FF / BN, NN / BM, BB), 256, G2_SMEM>>>(P, WhT, out, invden);
}